// round 1
// baseline (speedup 1.0000x reference)
#include <cuda_runtime.h>

// Problem constants
#define B_      16
#define C_      512
#define HW_     4096
#define INNER_  256
#define HW4     1024        // HW_/4 (float4 units per channel)

// Pass-kernel tiling
#define NTILE   4           // pixel tiles per batch (1024 px each)
#define NCGRP   8           // channel groups per batch (64 ch each)
#define CG      64          // C_ / NCGRP
#define NT      256         // threads per pass CTA
#define NWARP   8           // NT/32
#define NPART   (NTILE*NWARP)  // 32 partials per (b,c)

// ---------------------------------------------------------------------------
// Scratch (static device globals; fully overwritten every call -> deterministic)
// ---------------------------------------------------------------------------
__device__ __align__(16) float g_cm_part [B_*NCGRP*HW_];   // 2 MB
__device__ __align__(16) float g_ctx_part[B_*NCGRP*HW_];   // 2 MB
__device__ __align__(16) float g_cm      [B_*HW_];         // softmaxed channel-attn map
__device__ __align__(16) float g_sigctx  [B_*HW_];         // sigmoid(spatial ctx)
__device__ float g_xsum_part[B_*C_*NPART];                 // 1 MB
__device__ float g_xw_part  [B_*C_*NPART];                 // 1 MB
__device__ float g_weff[B_*C_];
__device__ float g_mask[B_*C_];

// ---------------------------------------------------------------------------
// Block reductions (512-thread blocks)
// ---------------------------------------------------------------------------
__device__ __forceinline__ float blockReduceSum(float v) {
    __shared__ float s[17];
    const int lane = threadIdx.x & 31, wid = threadIdx.x >> 5;
    #pragma unroll
    for (int o = 16; o; o >>= 1) v += __shfl_down_sync(0xffffffffu, v, o);
    if (lane == 0) s[wid] = v;
    __syncthreads();
    if (wid == 0) {
        float t = (lane < (int)(blockDim.x >> 5)) ? s[lane] : 0.0f;
        #pragma unroll
        for (int o = 8; o; o >>= 1) t += __shfl_down_sync(0xffffffffu, t, o);
        if (lane == 0) s[16] = t;
    }
    __syncthreads();
    float r = s[16];
    __syncthreads();
    return r;
}

__device__ __forceinline__ float blockReduceMax(float v) {
    __shared__ float s[17];
    const int lane = threadIdx.x & 31, wid = threadIdx.x >> 5;
    #pragma unroll
    for (int o = 16; o; o >>= 1) v = fmaxf(v, __shfl_down_sync(0xffffffffu, v, o));
    if (lane == 0) s[wid] = v;
    __syncthreads();
    if (wid == 0) {
        float t = (lane < (int)(blockDim.x >> 5)) ? s[lane] : -1e30f;
        #pragma unroll
        for (int o = 8; o; o >>= 1) t = fmaxf(t, __shfl_down_sync(0xffffffffu, t, o));
        if (lane == 0) s[16] = t;
    }
    __syncthreads();
    float r = s[16];
    __syncthreads();
    return r;
}

// ---------------------------------------------------------------------------
// Pass 1: stream x once -> cm_raw partials (per pixel) + xsum partials (per ch)
// grid: (NTILE*NCGRP, B_), block: NT
// ---------------------------------------------------------------------------
__global__ __launch_bounds__(NT)
void k_pass1(const float* __restrict__ x, const float* __restrict__ Wcq) {
    const int b    = blockIdx.y;
    const int tile = blockIdx.x >> 3;   // /NCGRP
    const int g    = blockIdx.x & 7;
    const int tid  = threadIdx.x;
    const int lane = tid & 31, warp = tid >> 5;

    __shared__ float s_w[CG];
    if (tid < CG) s_w[tid] = Wcq[g*CG + tid];
    __syncthreads();

    const float4* x4 = reinterpret_cast<const float4*>(x);
    const int pix4 = tile*NT + tid;                    // float4 index within channel
    const int base = (b*C_ + g*CG)*HW4 + pix4;

    float4 acc = make_float4(0.f, 0.f, 0.f, 0.f);
    #pragma unroll 4
    for (int ci = 0; ci < CG; ci++) {
        float4 v = x4[base + ci*HW4];
        float  q = s_w[ci];
        acc.x = fmaf(q, v.x, acc.x);
        acc.y = fmaf(q, v.y, acc.y);
        acc.z = fmaf(q, v.z, acc.z);
        acc.w = fmaf(q, v.w, acc.w);
        // per-channel pixel-sum partial (for xmean)
        float s = (v.x + v.y) + (v.z + v.w);
        s += __shfl_down_sync(0xffffffffu, s, 16);
        s += __shfl_down_sync(0xffffffffu, s, 8);
        s += __shfl_down_sync(0xffffffffu, s, 4);
        s += __shfl_down_sync(0xffffffffu, s, 2);
        s += __shfl_down_sync(0xffffffffu, s, 1);
        if (lane == 0)
            g_xsum_part[((b*C_ + g*CG + ci)*NTILE + tile)*NWARP + warp] = s;
    }
    reinterpret_cast<float4*>(g_cm_part)[(b*NCGRP + g)*HW4 + pix4] = acc;
}

// ---------------------------------------------------------------------------
// Mid 1 (per batch): softmax(cm) over HW; avg = softmax(Wsq @ xmean);
// w_eff = avg^T @ Wsv.   grid: B_, block: 512
// ---------------------------------------------------------------------------
__global__ __launch_bounds__(512)
void k_mid1(const float* __restrict__ Wsq, const float* __restrict__ Wsv) {
    const int b = blockIdx.x;
    const int tid = threadIdx.x;
    __shared__ float s_xmean[C_];
    __shared__ float s_avg[INNER_];

    // reduce xsum partials -> xmean
    {
        const float* p = g_xsum_part + (b*C_ + tid)*NPART;
        float s = 0.f;
        #pragma unroll
        for (int i = 0; i < NPART; i++) s += p[i];
        s_xmean[tid] = s * (1.0f/(float)HW_);
    }

    // softmax over HW (8 elems/thread)
    float v[8];
    float mx = -1e30f;
    #pragma unroll
    for (int j = 0; j < 8; j++) {
        int n = tid + j*512;
        float s = 0.f;
        #pragma unroll
        for (int g = 0; g < NCGRP; g++) s += g_cm_part[(b*NCGRP + g)*HW_ + n];
        v[j] = s;
        mx = fmaxf(mx, s);
    }
    mx = blockReduceMax(mx);
    float es = 0.f;
    #pragma unroll
    for (int j = 0; j < 8; j++) { v[j] = __expf(v[j] - mx); es += v[j]; }
    es = blockReduceSum(es);
    const float inv = 1.0f/es;
    #pragma unroll
    for (int j = 0; j < 8; j++) g_cm[b*HW_ + tid + j*512] = v[j]*inv;

    // avg_raw = Wsq @ xmean ; softmax over inner
    float a = -1e30f;
    if (tid < INNER_) {
        float acc = 0.f;
        #pragma unroll 4
        for (int c = 0; c < C_; c++) acc = fmaf(Wsq[tid*C_ + c], s_xmean[c], acc);
        a = acc;
    }
    float m2 = blockReduceMax(a);
    float e  = (tid < INNER_) ? __expf(a - m2) : 0.0f;
    float s2 = blockReduceSum(e);
    if (tid < INNER_) s_avg[tid] = e / s2;
    __syncthreads();

    // w_eff[c] = sum_k avg[k] * Wsv[k,c]  (coalesced in c)
    float w = 0.f;
    #pragma unroll 4
    for (int k = 0; k < INNER_; k++) w = fmaf(s_avg[k], Wsv[k*C_ + tid], w);
    g_weff[b*C_ + tid] = w;
}

// ---------------------------------------------------------------------------
// Pass 2: stream x again -> xw partials (per ch) + ctx partials (per pixel)
// ---------------------------------------------------------------------------
__global__ __launch_bounds__(NT)
void k_pass2(const float* __restrict__ x) {
    const int b    = blockIdx.y;
    const int tile = blockIdx.x >> 3;
    const int g    = blockIdx.x & 7;
    const int tid  = threadIdx.x;
    const int lane = tid & 31, warp = tid >> 5;

    __shared__ float s_w[CG];
    if (tid < CG) s_w[tid] = g_weff[b*C_ + g*CG + tid];
    __syncthreads();

    const float4* x4 = reinterpret_cast<const float4*>(x);
    const int pix4 = tile*NT + tid;
    const float4 cm = reinterpret_cast<const float4*>(g_cm)[b*HW4 + pix4];
    const int base = (b*C_ + g*CG)*HW4 + pix4;

    float4 ctx = make_float4(0.f, 0.f, 0.f, 0.f);
    #pragma unroll 4
    for (int ci = 0; ci < CG; ci++) {
        float4 v = x4[base + ci*HW4];
        float  w = s_w[ci];
        ctx.x = fmaf(w, v.x, ctx.x);
        ctx.y = fmaf(w, v.y, ctx.y);
        ctx.z = fmaf(w, v.z, ctx.z);
        ctx.w = fmaf(w, v.w, ctx.w);
        float t = v.x*cm.x + v.y*cm.y + v.z*cm.z + v.w*cm.w;
        t += __shfl_down_sync(0xffffffffu, t, 16);
        t += __shfl_down_sync(0xffffffffu, t, 8);
        t += __shfl_down_sync(0xffffffffu, t, 4);
        t += __shfl_down_sync(0xffffffffu, t, 2);
        t += __shfl_down_sync(0xffffffffu, t, 1);
        if (lane == 0)
            g_xw_part[((b*C_ + g*CG + ci)*NTILE + tile)*NWARP + warp] = t;
    }
    reinterpret_cast<float4*>(g_ctx_part)[(b*NCGRP + g)*HW4 + pix4] = ctx;
}

// ---------------------------------------------------------------------------
// Mid 2 (per batch): sig_ctx; context = Wcv@xw; z = Wcz@context;
// LayerNorm(z) -> mask = sigmoid.   grid: B_, block: 512
// ---------------------------------------------------------------------------
__global__ __launch_bounds__(512)
void k_mid2(const float* __restrict__ Wcv, const float* __restrict__ Wcz,
            const float* __restrict__ gamma, const float* __restrict__ beta) {
    const int b = blockIdx.x;
    const int tid = threadIdx.x;
    __shared__ float s_xw[C_];
    __shared__ float s_ctx[INNER_];

    {
        const float* p = g_xw_part + (b*C_ + tid)*NPART;
        float s = 0.f;
        #pragma unroll
        for (int i = 0; i < NPART; i++) s += p[i];
        s_xw[tid] = s;
    }

    // sig_ctx (8 per thread)
    #pragma unroll
    for (int j = 0; j < 8; j++) {
        int n = tid + j*512;
        float s = 0.f;
        #pragma unroll
        for (int g = 0; g < NCGRP; g++) s += g_ctx_part[(b*NCGRP + g)*HW_ + n];
        g_sigctx[b*HW_ + n] = 1.0f/(1.0f + __expf(-s));
    }
    __syncthreads();

    if (tid < INNER_) {
        float acc = 0.f;
        #pragma unroll 4
        for (int c = 0; c < C_; c++) acc = fmaf(Wcv[tid*C_ + c], s_xw[c], acc);
        s_ctx[tid] = acc;
    }
    __syncthreads();

    float z = 0.f;
    #pragma unroll 4
    for (int k = 0; k < INNER_; k++) z = fmaf(Wcz[tid*INNER_ + k], s_ctx[k], z);

    float mu  = blockReduceSum(z) * (1.0f/(float)C_);
    float d   = z - mu;
    float var = blockReduceSum(d*d) * (1.0f/(float)C_);
    float zn  = d * rsqrtf(var + 1e-5f) * gamma[tid] + beta[tid];
    g_mask[b*C_ + tid] = 1.0f/(1.0f + __expf(-zn));
}

// ---------------------------------------------------------------------------
// Final: out = x * (mask[b,c] + sig_ctx[b,n])
// ---------------------------------------------------------------------------
__global__ __launch_bounds__(256)
void k_final(const float* __restrict__ x, float* __restrict__ out) {
    const float4* x4  = reinterpret_cast<const float4*>(x);
    float4*       o4  = reinterpret_cast<float4*>(out);
    const float4* sc4 = reinterpret_cast<const float4*>(g_sigctx);
    const int total4 = B_*C_*HW4;
    for (int i = blockIdx.x*blockDim.x + threadIdx.x; i < total4;
         i += gridDim.x*blockDim.x) {
        const int n4 = i & (HW4 - 1);
        const int bc = i >> 10;          // b*512 + c
        const int b  = bc >> 9;
        const float  m = g_mask[bc];     // warp-uniform -> single sector
        const float4 s = sc4[(b << 10) + n4];
        float4 v = x4[i];
        float4 r;
        r.x = v.x*(m + s.x);
        r.y = v.y*(m + s.y);
        r.z = v.z*(m + s.z);
        r.w = v.w*(m + s.w);
        o4[i] = r;
    }
}

// ---------------------------------------------------------------------------
// Launch
// ---------------------------------------------------------------------------
extern "C" void kernel_launch(void* const* d_in, const int* in_sizes, int n_in,
                              void* d_out, int out_size) {
    const float* x     = (const float*)d_in[0];
    const float* Wsq   = (const float*)d_in[1];
    const float* Wsv   = (const float*)d_in[2];
    const float* Wcq   = (const float*)d_in[3];
    const float* Wcv   = (const float*)d_in[4];
    const float* Wcz   = (const float*)d_in[5];
    const float* gamma = (const float*)d_in[6];
    const float* beta  = (const float*)d_in[7];
    float* out = (float*)d_out;

    dim3 gpass(NTILE*NCGRP, B_);   // 32 x 16 = 512 CTAs
    k_pass1<<<gpass, NT>>>(x, Wcq);
    k_mid1 <<<B_, 512>>>(Wsq, Wsv);
    k_pass2<<<gpass, NT>>>(x);
    k_mid2 <<<B_, 512>>>(Wcv, Wcz, gamma, beta);
    k_final<<<8192, 256>>>(x, out);
}

// round 3
// speedup vs baseline: 1.7564x; 1.7564x over previous
#include <cuda_runtime.h>

// Problem constants
#define B_      16
#define C_      512
#define HW_     4096
#define INNER_  256
#define HW4     1024        // HW_/4 (float4 units per channel)

// Pass-kernel tiling
#define NTILE   4           // pixel tiles per batch (1024 px each)
#define NCGRP   8           // channel groups per batch (64 ch each)
#define CG      64          // C_ / NCGRP
#define NT      256         // threads per pass CTA
#define NWARP   8           // NT/32
#define NPART   (NTILE*NWARP)  // 32 partials per (b,c)
#define MIDW    16          // warps per mid-kernel CTA (512 threads)

// ---------------------------------------------------------------------------
// Scratch (static device globals; fully overwritten every call -> deterministic)
// ---------------------------------------------------------------------------
__device__ __align__(16) float g_cm_part [B_*NCGRP*HW_];   // 2 MB
__device__ __align__(16) float g_ctx_part[B_*NCGRP*HW_];   // 2 MB
__device__ __align__(16) float g_cm      [B_*HW_];         // softmaxed channel-attn map
__device__ __align__(16) float g_sigctx  [B_*HW_];         // sigmoid(spatial ctx)
__device__ __align__(16) float g_xsum_part[B_*C_*NPART];   // 1 MB
__device__ __align__(16) float g_xw_part  [B_*C_*NPART];   // 1 MB
__device__ float g_weff[B_*C_];
__device__ float g_mask[B_*C_];

// ---------------------------------------------------------------------------
// Reductions
// ---------------------------------------------------------------------------
__device__ __forceinline__ float warpReduceSum(float v) {
    #pragma unroll
    for (int o = 16; o; o >>= 1) v += __shfl_down_sync(0xffffffffu, v, o);
    return v;
}

__device__ __forceinline__ float blockReduceSum(float v) {
    __shared__ float s[17];
    const int lane = threadIdx.x & 31, wid = threadIdx.x >> 5;
    v = warpReduceSum(v);
    if (lane == 0) s[wid] = v;
    __syncthreads();
    if (wid == 0) {
        float t = (lane < (int)(blockDim.x >> 5)) ? s[lane] : 0.0f;
        #pragma unroll
        for (int o = 8; o; o >>= 1) t += __shfl_down_sync(0xffffffffu, t, o);
        if (lane == 0) s[16] = t;
    }
    __syncthreads();
    float r = s[16];
    __syncthreads();
    return r;
}

__device__ __forceinline__ float blockReduceMax(float v) {
    __shared__ float s[17];
    const int lane = threadIdx.x & 31, wid = threadIdx.x >> 5;
    #pragma unroll
    for (int o = 16; o; o >>= 1) v = fmaxf(v, __shfl_down_sync(0xffffffffu, v, o));
    if (lane == 0) s[wid] = v;
    __syncthreads();
    if (wid == 0) {
        float t = (lane < (int)(blockDim.x >> 5)) ? s[lane] : -1e30f;
        #pragma unroll
        for (int o = 8; o; o >>= 1) t = fmaxf(t, __shfl_down_sync(0xffffffffu, t, o));
        if (lane == 0) s[16] = t;
    }
    __syncthreads();
    float r = s[16];
    __syncthreads();
    return r;
}

__device__ __forceinline__ float dot4(float4 a, float4 b) {
    return fmaf(a.x, b.x, fmaf(a.y, b.y, fmaf(a.z, b.z, a.w * b.w)));
}

// ---------------------------------------------------------------------------
// Pass 1: stream x once -> cm_raw partials (per pixel) + xsum partials (per ch)
// grid: (NTILE*NCGRP, B_), block: NT
// ---------------------------------------------------------------------------
__global__ __launch_bounds__(NT)
void k_pass1(const float* __restrict__ x, const float* __restrict__ Wcq) {
    const int b    = blockIdx.y;
    const int tile = blockIdx.x >> 3;   // /NCGRP
    const int g    = blockIdx.x & 7;
    const int tid  = threadIdx.x;
    const int lane = tid & 31, warp = tid >> 5;

    __shared__ float s_w[CG];
    if (tid < CG) s_w[tid] = Wcq[g*CG + tid];
    __syncthreads();

    const float4* x4 = reinterpret_cast<const float4*>(x);
    const int pix4 = tile*NT + tid;                    // float4 index within channel
    const int base = (b*C_ + g*CG)*HW4 + pix4;

    float4 acc = make_float4(0.f, 0.f, 0.f, 0.f);
    #pragma unroll 4
    for (int ci = 0; ci < CG; ci++) {
        float4 v = x4[base + ci*HW4];
        float  q = s_w[ci];
        acc.x = fmaf(q, v.x, acc.x);
        acc.y = fmaf(q, v.y, acc.y);
        acc.z = fmaf(q, v.z, acc.z);
        acc.w = fmaf(q, v.w, acc.w);
        // per-channel pixel-sum partial (for xmean)
        float s = (v.x + v.y) + (v.z + v.w);
        s = warpReduceSum(s);
        if (lane == 0)
            g_xsum_part[((b*C_ + g*CG + ci)*NTILE + tile)*NWARP + warp] = s;
    }
    reinterpret_cast<float4*>(g_cm_part)[(b*NCGRP + g)*HW4 + pix4] = acc;
}

// ---------------------------------------------------------------------------
// Mid 1 (per batch): softmax(cm) over HW; avg = softmax(Wsq @ xmean);
// w_eff = avg^T @ Wsv.   grid: B_, block: 512
// ---------------------------------------------------------------------------
__global__ __launch_bounds__(512)
void k_mid1(const float* __restrict__ Wsq, const float* __restrict__ Wsv) {
    const int b = blockIdx.x;
    const int tid  = threadIdx.x;
    const int lane = tid & 31, warp = tid >> 5;
    __shared__ __align__(16) float s_xmean[C_];
    __shared__ __align__(16) float s_a[INNER_];
    __shared__ __align__(16) float s_avg[INNER_];

    // reduce xsum partials -> xmean (32 contiguous floats/thread, float4)
    {
        const float4* p = reinterpret_cast<const float4*>(g_xsum_part + (b*C_ + tid)*NPART);
        float s = 0.f;
        #pragma unroll
        for (int i = 0; i < NPART/4; i++) {
            float4 v = p[i];
            s += (v.x + v.y) + (v.z + v.w);
        }
        s_xmean[tid] = s * (1.0f/(float)HW_);
    }
    __syncthreads();

    // avg_raw = Wsq @ xmean : warp-per-row, lane-coalesced float4 loads
    const float4* xm4 = reinterpret_cast<const float4*>(s_xmean);
    for (int row = warp; row < INNER_; row += MIDW) {
        const float4* wr = reinterpret_cast<const float4*>(Wsq + row*C_);
        float acc = 0.f;
        #pragma unroll
        for (int j = 0; j < C_/(4*32); j++)
            acc += dot4(wr[lane + 32*j], xm4[lane + 32*j]);
        acc = warpReduceSum(acc);
        if (lane == 0) s_a[row] = acc;
    }

    // softmax over HW (8 elems/thread) — coalesced reads of cm partials
    float v[8];
    float mx = -1e30f;
    #pragma unroll
    for (int j = 0; j < 8; j++) {
        int n = tid + j*512;
        float s = 0.f;
        #pragma unroll
        for (int g = 0; g < NCGRP; g++) s += g_cm_part[(b*NCGRP + g)*HW_ + n];
        v[j] = s;
        mx = fmaxf(mx, s);
    }
    mx = blockReduceMax(mx);
    float es = 0.f;
    #pragma unroll
    for (int j = 0; j < 8; j++) { v[j] = __expf(v[j] - mx); es += v[j]; }
    es = blockReduceSum(es);
    const float inv = 1.0f/es;
    #pragma unroll
    for (int j = 0; j < 8; j++) g_cm[b*HW_ + tid + j*512] = v[j]*inv;

    // softmax over inner on s_a
    float a = (tid < INNER_) ? s_a[tid] : -1e30f;
    float m2 = blockReduceMax(a);
    float e  = (tid < INNER_) ? __expf(a - m2) : 0.0f;
    float s2 = blockReduceSum(e);
    if (tid < INNER_) s_avg[tid] = e / s2;
    __syncthreads();

    // w_eff[c] = sum_k avg[k] * Wsv[k,c]  (coalesced in c)
    float w = 0.f;
    #pragma unroll 4
    for (int k = 0; k < INNER_; k++) w = fmaf(s_avg[k], Wsv[k*C_ + tid], w);
    g_weff[b*C_ + tid] = w;
}

// ---------------------------------------------------------------------------
// Pass 2: stream x again -> xw partials (per ch) + ctx partials (per pixel)
// ---------------------------------------------------------------------------
__global__ __launch_bounds__(NT)
void k_pass2(const float* __restrict__ x) {
    const int b    = blockIdx.y;
    const int tile = blockIdx.x >> 3;
    const int g    = blockIdx.x & 7;
    const int tid  = threadIdx.x;
    const int lane = tid & 31, warp = tid >> 5;

    __shared__ float s_w[CG];
    if (tid < CG) s_w[tid] = g_weff[b*C_ + g*CG + tid];
    __syncthreads();

    const float4* x4 = reinterpret_cast<const float4*>(x);
    const int pix4 = tile*NT + tid;
    const float4 cm = reinterpret_cast<const float4*>(g_cm)[b*HW4 + pix4];
    const int base = (b*C_ + g*CG)*HW4 + pix4;

    float4 ctx = make_float4(0.f, 0.f, 0.f, 0.f);
    #pragma unroll 4
    for (int ci = 0; ci < CG; ci++) {
        float4 v = x4[base + ci*HW4];
        float  w = s_w[ci];
        ctx.x = fmaf(w, v.x, ctx.x);
        ctx.y = fmaf(w, v.y, ctx.y);
        ctx.z = fmaf(w, v.z, ctx.z);
        ctx.w = fmaf(w, v.w, ctx.w);
        float t = v.x*cm.x + v.y*cm.y + v.z*cm.z + v.w*cm.w;
        t = warpReduceSum(t);
        if (lane == 0)
            g_xw_part[((b*C_ + g*CG + ci)*NTILE + tile)*NWARP + warp] = t;
    }
    reinterpret_cast<float4*>(g_ctx_part)[(b*NCGRP + g)*HW4 + pix4] = ctx;
}

// ---------------------------------------------------------------------------
// Mid 2 (per batch): sig_ctx; context = Wcv@xw; z = Wcz@context;
// LayerNorm(z) -> mask = sigmoid.   grid: B_, block: 512
// ---------------------------------------------------------------------------
__global__ __launch_bounds__(512)
void k_mid2(const float* __restrict__ Wcv, const float* __restrict__ Wcz,
            const float* __restrict__ gamma, const float* __restrict__ beta) {
    const int b = blockIdx.x;
    const int tid  = threadIdx.x;
    const int lane = tid & 31, warp = tid >> 5;
    __shared__ __align__(16) float s_xw[C_];
    __shared__ __align__(16) float s_ctx[INNER_];
    __shared__ __align__(16) float s_z[C_];

    // reduce xw partials (32 contiguous floats/thread, float4)
    {
        const float4* p = reinterpret_cast<const float4*>(g_xw_part + (b*C_ + tid)*NPART);
        float s = 0.f;
        #pragma unroll
        for (int i = 0; i < NPART/4; i++) {
            float4 v = p[i];
            s += (v.x + v.y) + (v.z + v.w);
        }
        s_xw[tid] = s;
    }
    __syncthreads();

    // context[k] = Wcv[k,:] . xw : warp-per-row, coalesced float4
    const float4* xw4 = reinterpret_cast<const float4*>(s_xw);
    for (int row = warp; row < INNER_; row += MIDW) {
        const float4* wr = reinterpret_cast<const float4*>(Wcv + row*C_);
        float acc = 0.f;
        #pragma unroll
        for (int j = 0; j < C_/(4*32); j++)
            acc += dot4(wr[lane + 32*j], xw4[lane + 32*j]);
        acc = warpReduceSum(acc);
        if (lane == 0) s_ctx[row] = acc;
    }

    // sig_ctx (8 per thread) — overlaps with context GEMV latency
    #pragma unroll
    for (int j = 0; j < 8; j++) {
        int n = tid + j*512;
        float s = 0.f;
        #pragma unroll
        for (int g = 0; g < NCGRP; g++) s += g_ctx_part[(b*NCGRP + g)*HW_ + n];
        g_sigctx[b*HW_ + n] = 1.0f/(1.0f + __expf(-s));
    }
    __syncthreads();

    // z[o] = Wcz[o,:] . ctx : warp-per-row, coalesced float4
    const float4* ctx4 = reinterpret_cast<const float4*>(s_ctx);
    for (int row = warp; row < C_; row += MIDW) {
        const float4* wr = reinterpret_cast<const float4*>(Wcz + row*INNER_);
        float acc = 0.f;
        #pragma unroll
        for (int j = 0; j < INNER_/(4*32); j++)
            acc += dot4(wr[lane + 32*j], ctx4[lane + 32*j]);
        acc = warpReduceSum(acc);
        if (lane == 0) s_z[row] = acc;
    }
    __syncthreads();

    float z = s_z[tid];
    float mu  = blockReduceSum(z) * (1.0f/(float)C_);
    float d   = z - mu;
    float var = blockReduceSum(d*d) * (1.0f/(float)C_);
    float zn  = d * rsqrtf(var + 1e-5f) * gamma[tid] + beta[tid];
    g_mask[b*C_ + tid] = 1.0f/(1.0f + __expf(-zn));
}

// ---------------------------------------------------------------------------
// Final: out = x * (mask[b,c] + sig_ctx[b,n])
// ---------------------------------------------------------------------------
__global__ __launch_bounds__(256)
void k_final(const float* __restrict__ x, float* __restrict__ out) {
    const float4* x4  = reinterpret_cast<const float4*>(x);
    float4*       o4  = reinterpret_cast<float4*>(out);
    const float4* sc4 = reinterpret_cast<const float4*>(g_sigctx);
    const int total4 = B_*C_*HW4;
    for (int i = blockIdx.x*blockDim.x + threadIdx.x; i < total4;
         i += gridDim.x*blockDim.x) {
        const int n4 = i & (HW4 - 1);
        const int bc = i >> 10;          // b*512 + c
        const int b  = bc >> 9;
        const float  m = g_mask[bc];     // warp-uniform -> single sector
        const float4 s = sc4[(b << 10) + n4];
        float4 v = x4[i];
        float4 r;
        r.x = v.x*(m + s.x);
        r.y = v.y*(m + s.y);
        r.z = v.z*(m + s.z);
        r.w = v.w*(m + s.w);
        o4[i] = r;
    }
}

// ---------------------------------------------------------------------------
// Launch
// ---------------------------------------------------------------------------
extern "C" void kernel_launch(void* const* d_in, const int* in_sizes, int n_in,
                              void* d_out, int out_size) {
    const float* x     = (const float*)d_in[0];
    const float* Wsq   = (const float*)d_in[1];
    const float* Wsv   = (const float*)d_in[2];
    const float* Wcq   = (const float*)d_in[3];
    const float* Wcv   = (const float*)d_in[4];
    const float* Wcz   = (const float*)d_in[5];
    const float* gamma = (const float*)d_in[6];
    const float* beta  = (const float*)d_in[7];
    float* out = (float*)d_out;

    dim3 gpass(NTILE*NCGRP, B_);   // 32 x 16 = 512 CTAs
    k_pass1<<<gpass, NT>>>(x, Wcq);
    k_mid1 <<<B_, 512>>>(Wsq, Wsv);
    k_pass2<<<gpass, NT>>>(x);
    k_mid2 <<<B_, 512>>>(Wcv, Wcz, gamma, beta);
    k_final<<<8192, 256>>>(x, out);
}

// round 4
// speedup vs baseline: 1.9167x; 1.0912x over previous
#include <cuda_runtime.h>

// Problem constants
#define B_      16
#define C_      512
#define HW_     4096
#define INNER_  256
#define HW4     1024        // HW_/4 (float4 units per channel)

// Pass-kernel tiling
#define NTILE   4           // pixel tiles per batch (1024 px each)
#define NCGRP   8           // channel groups per batch (64 ch each)
#define CG      64          // C_ / NCGRP
#define NT      256         // threads per pass CTA
#define NWARP   8           // NT/32
#define NPART   (NTILE*NWARP)  // 32 partials per (b,c)
#define MIDW    16          // warps per mid-kernel CTA (512 threads)

// ---------------------------------------------------------------------------
// Scratch (static device globals; fully overwritten every call -> deterministic)
// ---------------------------------------------------------------------------
__device__ __align__(16) float g_cm_part [B_*NCGRP*HW_];   // 2 MB
__device__ __align__(16) float g_ctx_part[B_*NCGRP*HW_];   // 2 MB
__device__ __align__(16) float g_cm      [B_*HW_];         // exp(cm_raw), UNNORMALIZED
__device__ __align__(16) float g_sigctx  [B_*HW_];         // sigmoid(spatial ctx)
__device__ __align__(16) float g_xsum_part[B_*C_*NPART];   // 1 MB
__device__ __align__(16) float g_xw_part  [B_*C_*NPART];   // 1 MB
__device__ __align__(16) float g_xmean[B_*C_];
__device__ __align__(16) float g_xw   [B_*C_];             // unnormalized x@exp(cm)
__device__ float g_Zc_part[B_*4];                          // exp-sum partials per batch
__device__ float g_weff[B_*C_];
__device__ float g_mask[B_*C_];

// ---------------------------------------------------------------------------
// Reductions
// ---------------------------------------------------------------------------
__device__ __forceinline__ float warpReduceSum(float v) {
    #pragma unroll
    for (int o = 16; o; o >>= 1) v += __shfl_down_sync(0xffffffffu, v, o);
    return v;
}

__device__ __forceinline__ float blockReduceSum(float v) {
    __shared__ float s[17];
    const int lane = threadIdx.x & 31, wid = threadIdx.x >> 5;
    v = warpReduceSum(v);
    if (lane == 0) s[wid] = v;
    __syncthreads();
    if (wid == 0) {
        float t = (lane < (int)(blockDim.x >> 5)) ? s[lane] : 0.0f;
        #pragma unroll
        for (int o = 8; o; o >>= 1) t += __shfl_down_sync(0xffffffffu, t, o);
        if (lane == 0) s[16] = t;
    }
    __syncthreads();
    float r = s[16];
    __syncthreads();
    return r;
}

__device__ __forceinline__ float blockReduceMax(float v) {
    __shared__ float s[17];
    const int lane = threadIdx.x & 31, wid = threadIdx.x >> 5;
    #pragma unroll
    for (int o = 16; o; o >>= 1) v = fmaxf(v, __shfl_down_sync(0xffffffffu, v, o));
    if (lane == 0) s[wid] = v;
    __syncthreads();
    if (wid == 0) {
        float t = (lane < (int)(blockDim.x >> 5)) ? s[lane] : -1e30f;
        #pragma unroll
        for (int o = 8; o; o >>= 1) t = fmaxf(t, __shfl_down_sync(0xffffffffu, t, o));
        if (lane == 0) s[16] = t;
    }
    __syncthreads();
    float r = s[16];
    __syncthreads();
    return r;
}

__device__ __forceinline__ float dot4(float4 a, float4 b) {
    return fmaf(a.x, b.x, fmaf(a.y, b.y, fmaf(a.z, b.z, a.w * b.w)));
}

// ---------------------------------------------------------------------------
// Pass 1: stream x once -> cm_raw partials (per pixel) + xsum partials (per ch)
// grid: (NTILE*NCGRP, B_), block: NT
// ---------------------------------------------------------------------------
__global__ __launch_bounds__(NT)
void k_pass1(const float* __restrict__ x, const float* __restrict__ Wcq) {
    const int b    = blockIdx.y;
    const int tile = blockIdx.x >> 3;   // /NCGRP
    const int g    = blockIdx.x & 7;
    const int tid  = threadIdx.x;
    const int lane = tid & 31, warp = tid >> 5;

    __shared__ float s_w[CG];
    if (tid < CG) s_w[tid] = Wcq[g*CG + tid];
    __syncthreads();

    const float4* x4 = reinterpret_cast<const float4*>(x);
    const int pix4 = tile*NT + tid;                    // float4 index within channel
    const int base = (b*C_ + g*CG)*HW4 + pix4;

    float4 acc = make_float4(0.f, 0.f, 0.f, 0.f);
    #pragma unroll 4
    for (int ci = 0; ci < CG; ci++) {
        float4 v = x4[base + ci*HW4];
        float  q = s_w[ci];
        acc.x = fmaf(q, v.x, acc.x);
        acc.y = fmaf(q, v.y, acc.y);
        acc.z = fmaf(q, v.z, acc.z);
        acc.w = fmaf(q, v.w, acc.w);
        // per-channel pixel-sum partial (for xmean)
        float s = (v.x + v.y) + (v.z + v.w);
        s = warpReduceSum(s);
        if (lane == 0)
            g_xsum_part[((b*C_ + g*CG + ci)*NTILE + tile)*NWARP + warp] = s;
    }
    reinterpret_cast<float4*>(g_cm_part)[(b*NCGRP + g)*HW4 + pix4] = acc;
}

// ---------------------------------------------------------------------------
// Red 1 (wide): grid (5, B_), block 256.
//   bx<4 : reduce cm partials -> g_cm = exp(raw), per-CTA expsum -> g_Zc_part
//   bx==4: reduce xsum partials -> g_xmean
// ---------------------------------------------------------------------------
__global__ __launch_bounds__(256)
void k_red1() {
    const int b  = blockIdx.y;
    const int bx = blockIdx.x;
    const int tid = threadIdx.x;

    if (bx < 4) {
        const int pix4 = bx*256 + tid;       // float4 index in [0,HW4)
        const float4* cp = reinterpret_cast<const float4*>(g_cm_part);
        float4 s = make_float4(0.f, 0.f, 0.f, 0.f);
        #pragma unroll
        for (int g = 0; g < NCGRP; g++) {
            float4 v = cp[(b*NCGRP + g)*HW4 + pix4];
            s.x += v.x; s.y += v.y; s.z += v.z; s.w += v.w;
        }
        float4 e;
        e.x = __expf(s.x); e.y = __expf(s.y);
        e.z = __expf(s.z); e.w = __expf(s.w);
        reinterpret_cast<float4*>(g_cm)[b*HW4 + pix4] = e;
        float zs = blockReduceSum((e.x + e.y) + (e.z + e.w));
        if (tid == 0) g_Zc_part[b*4 + bx] = zs;
    } else {
        // 512 channels, 256 threads -> 2 each; each sums 32 contiguous floats
        for (int c = tid; c < C_; c += 256) {
            const float4* p = reinterpret_cast<const float4*>(
                g_xsum_part + (b*C_ + c)*NPART);
            float s = 0.f;
            #pragma unroll
            for (int i = 0; i < NPART/4; i++) {
                float4 v = p[i];
                s += (v.x + v.y) + (v.z + v.w);
            }
            g_xmean[b*C_ + c] = s * (1.0f/(float)HW_);
        }
    }
}

// ---------------------------------------------------------------------------
// Mid 1 (per batch): avg = softmax(Wsq @ xmean); w_eff = avg^T @ Wsv.
// grid: B_, block: 512
// ---------------------------------------------------------------------------
__global__ __launch_bounds__(512)
void k_mid1(const float* __restrict__ Wsq, const float* __restrict__ Wsv) {
    const int b = blockIdx.x;
    const int tid  = threadIdx.x;
    const int lane = tid & 31, warp = tid >> 5;
    __shared__ __align__(16) float s_xmean[C_];
    __shared__ __align__(16) float s_a[INNER_];
    __shared__ __align__(16) float s_avg[INNER_];

    s_xmean[tid] = g_xmean[b*C_ + tid];
    __syncthreads();

    // avg_raw = Wsq @ xmean : warp-per-row, lane-coalesced float4 loads
    const float4* xm4 = reinterpret_cast<const float4*>(s_xmean);
    for (int row = warp; row < INNER_; row += MIDW) {
        const float4* wr = reinterpret_cast<const float4*>(Wsq + row*C_);
        float acc = 0.f;
        #pragma unroll
        for (int j = 0; j < C_/(4*32); j++)
            acc += dot4(wr[lane + 32*j], xm4[lane + 32*j]);
        acc = warpReduceSum(acc);
        if (lane == 0) s_a[row] = acc;
    }
    __syncthreads();

    // softmax over inner
    float a = (tid < INNER_) ? s_a[tid] : -1e30f;
    float m2 = blockReduceMax(a);
    float e  = (tid < INNER_) ? __expf(a - m2) : 0.0f;
    float s2 = blockReduceSum(e);
    if (tid < INNER_) s_avg[tid] = e / s2;
    __syncthreads();

    // w_eff[c] = sum_k avg[k] * Wsv[k,c]  (coalesced in c)
    float w = 0.f;
    #pragma unroll 4
    for (int k = 0; k < INNER_; k++) w = fmaf(s_avg[k], Wsv[k*C_ + tid], w);
    g_weff[b*C_ + tid] = w;
}

// ---------------------------------------------------------------------------
// Pass 2: stream x again -> xw partials (unnormalized, vs exp(cm)) + ctx partials
// ---------------------------------------------------------------------------
__global__ __launch_bounds__(NT)
void k_pass2(const float* __restrict__ x) {
    const int b    = blockIdx.y;
    const int tile = blockIdx.x >> 3;
    const int g    = blockIdx.x & 7;
    const int tid  = threadIdx.x;
    const int lane = tid & 31, warp = tid >> 5;

    __shared__ float s_w[CG];
    if (tid < CG) s_w[tid] = g_weff[b*C_ + g*CG + tid];
    __syncthreads();

    const float4* x4 = reinterpret_cast<const float4*>(x);
    const int pix4 = tile*NT + tid;
    const float4 cm = reinterpret_cast<const float4*>(g_cm)[b*HW4 + pix4];
    const int base = (b*C_ + g*CG)*HW4 + pix4;

    float4 ctx = make_float4(0.f, 0.f, 0.f, 0.f);
    #pragma unroll 4
    for (int ci = 0; ci < CG; ci++) {
        float4 v = x4[base + ci*HW4];
        float  w = s_w[ci];
        ctx.x = fmaf(w, v.x, ctx.x);
        ctx.y = fmaf(w, v.y, ctx.y);
        ctx.z = fmaf(w, v.z, ctx.z);
        ctx.w = fmaf(w, v.w, ctx.w);
        float t = v.x*cm.x + v.y*cm.y + v.z*cm.z + v.w*cm.w;
        t = warpReduceSum(t);
        if (lane == 0)
            g_xw_part[((b*C_ + g*CG + ci)*NTILE + tile)*NWARP + warp] = t;
    }
    reinterpret_cast<float4*>(g_ctx_part)[(b*NCGRP + g)*HW4 + pix4] = ctx;
}

// ---------------------------------------------------------------------------
// Red 2 (wide): grid (5, B_), block 256.
//   bx<4 : reduce ctx partials -> g_sigctx = sigmoid(sum)
//   bx==4: reduce xw partials -> g_xw (unnormalized)
// ---------------------------------------------------------------------------
__global__ __launch_bounds__(256)
void k_red2() {
    const int b  = blockIdx.y;
    const int bx = blockIdx.x;
    const int tid = threadIdx.x;

    if (bx < 4) {
        const int pix4 = bx*256 + tid;
        const float4* cp = reinterpret_cast<const float4*>(g_ctx_part);
        float4 s = make_float4(0.f, 0.f, 0.f, 0.f);
        #pragma unroll
        for (int g = 0; g < NCGRP; g++) {
            float4 v = cp[(b*NCGRP + g)*HW4 + pix4];
            s.x += v.x; s.y += v.y; s.z += v.z; s.w += v.w;
        }
        float4 r;
        r.x = 1.0f/(1.0f + __expf(-s.x));
        r.y = 1.0f/(1.0f + __expf(-s.y));
        r.z = 1.0f/(1.0f + __expf(-s.z));
        r.w = 1.0f/(1.0f + __expf(-s.w));
        reinterpret_cast<float4*>(g_sigctx)[b*HW4 + pix4] = r;
    } else {
        for (int c = tid; c < C_; c += 256) {
            const float4* p = reinterpret_cast<const float4*>(
                g_xw_part + (b*C_ + c)*NPART);
            float s = 0.f;
            #pragma unroll
            for (int i = 0; i < NPART/4; i++) {
                float4 v = p[i];
                s += (v.x + v.y) + (v.z + v.w);
            }
            g_xw[b*C_ + c] = s;
        }
    }
}

// ---------------------------------------------------------------------------
// Mid 2 (per batch): xw_norm = xw/Zc; context = Wcv@xw_norm; z = Wcz@context;
// LayerNorm(z) -> mask = sigmoid.   grid: B_, block: 512
// ---------------------------------------------------------------------------
__global__ __launch_bounds__(512)
void k_mid2(const float* __restrict__ Wcv, const float* __restrict__ Wcz,
            const float* __restrict__ gamma, const float* __restrict__ beta) {
    const int b = blockIdx.x;
    const int tid  = threadIdx.x;
    const int lane = tid & 31, warp = tid >> 5;
    __shared__ __align__(16) float s_xw[C_];
    __shared__ __align__(16) float s_ctx[INNER_];
    __shared__ __align__(16) float s_z[C_];

    // softmax normalizer (deferred): 1/Z
    const float invZ = 1.0f / (g_Zc_part[b*4+0] + g_Zc_part[b*4+1] +
                               g_Zc_part[b*4+2] + g_Zc_part[b*4+3]);
    s_xw[tid] = g_xw[b*C_ + tid] * invZ;
    __syncthreads();

    // context[k] = Wcv[k,:] . xw : warp-per-row, coalesced float4
    const float4* xw4 = reinterpret_cast<const float4*>(s_xw);
    for (int row = warp; row < INNER_; row += MIDW) {
        const float4* wr = reinterpret_cast<const float4*>(Wcv + row*C_);
        float acc = 0.f;
        #pragma unroll
        for (int j = 0; j < C_/(4*32); j++)
            acc += dot4(wr[lane + 32*j], xw4[lane + 32*j]);
        acc = warpReduceSum(acc);
        if (lane == 0) s_ctx[row] = acc;
    }
    __syncthreads();

    // z[o] = Wcz[o,:] . ctx : warp-per-row, coalesced float4
    const float4* ctx4 = reinterpret_cast<const float4*>(s_ctx);
    for (int row = warp; row < C_; row += MIDW) {
        const float4* wr = reinterpret_cast<const float4*>(Wcz + row*INNER_);
        float acc = 0.f;
        #pragma unroll
        for (int j = 0; j < INNER_/(4*32); j++)
            acc += dot4(wr[lane + 32*j], ctx4[lane + 32*j]);
        acc = warpReduceSum(acc);
        if (lane == 0) s_z[row] = acc;
    }
    __syncthreads();

    float z = s_z[tid];
    float mu  = blockReduceSum(z) * (1.0f/(float)C_);
    float d   = z - mu;
    float var = blockReduceSum(d*d) * (1.0f/(float)C_);
    float zn  = d * rsqrtf(var + 1e-5f) * gamma[tid] + beta[tid];
    g_mask[b*C_ + tid] = 1.0f/(1.0f + __expf(-zn));
}

// ---------------------------------------------------------------------------
// Final: out = x * (mask[b,c] + sig_ctx[b,n])
// ---------------------------------------------------------------------------
__global__ __launch_bounds__(256)
void k_final(const float* __restrict__ x, float* __restrict__ out) {
    const float4* x4  = reinterpret_cast<const float4*>(x);
    float4*       o4  = reinterpret_cast<float4*>(out);
    const float4* sc4 = reinterpret_cast<const float4*>(g_sigctx);
    const int total4 = B_*C_*HW4;
    for (int i = blockIdx.x*blockDim.x + threadIdx.x; i < total4;
         i += gridDim.x*blockDim.x) {
        const int n4 = i & (HW4 - 1);
        const int bc = i >> 10;          // b*512 + c
        const int b  = bc >> 9;
        const float  m = g_mask[bc];     // warp-uniform -> single sector
        const float4 s = sc4[(b << 10) + n4];
        float4 v = x4[i];
        float4 r;
        r.x = v.x*(m + s.x);
        r.y = v.y*(m + s.y);
        r.z = v.z*(m + s.z);
        r.w = v.w*(m + s.w);
        o4[i] = r;
    }
}

// ---------------------------------------------------------------------------
// Launch
// ---------------------------------------------------------------------------
extern "C" void kernel_launch(void* const* d_in, const int* in_sizes, int n_in,
                              void* d_out, int out_size) {
    const float* x     = (const float*)d_in[0];
    const float* Wsq   = (const float*)d_in[1];
    const float* Wsv   = (const float*)d_in[2];
    const float* Wcq   = (const float*)d_in[3];
    const float* Wcv   = (const float*)d_in[4];
    const float* Wcz   = (const float*)d_in[5];
    const float* gamma = (const float*)d_in[6];
    const float* beta  = (const float*)d_in[7];
    float* out = (float*)d_out;

    dim3 gpass(NTILE*NCGRP, B_);   // 32 x 16 = 512 CTAs
    dim3 gred(5, B_);              // 80 CTAs
    k_pass1<<<gpass, NT>>>(x, Wcq);
    k_red1 <<<gred, 256>>>();
    k_mid1 <<<B_, 512>>>(Wsq, Wsv);
    k_pass2<<<gpass, NT>>>(x);
    k_red2 <<<gred, 256>>>();
    k_mid2 <<<B_, 512>>>(Wcv, Wcz, gamma, beta);
    k_final<<<8192, 256>>>(x, out);
}

// round 5
// speedup vs baseline: 2.3749x; 1.2391x over previous
#include <cuda_runtime.h>

// Problem constants
#define B_      16
#define C_      512
#define HW_     4096
#define INNER_  256
#define HW4     1024        // HW_/4 (float4 units per channel)

// Pass-kernel tiling
#define NTILE   8           // pixel tiles per batch (512 px each)
#define NCGRP   8           // channel groups per batch (64 ch each)
#define CG      64          // C_ / NCGRP
#define NT      128         // threads per pass CTA
#define NWARP   4           // NT/32
#define NPART   (NTILE*NWARP)  // 32 partials per (b,c)

// ---------------------------------------------------------------------------
// Scratch (static device globals; fully overwritten every call -> deterministic)
// ---------------------------------------------------------------------------
__device__ __align__(16) float g_cm_part [B_*NCGRP*HW_];   // 2 MB
__device__ __align__(16) float g_ctx_part[B_*NCGRP*HW_];   // 2 MB
__device__ __align__(16) float g_cm      [B_*HW_];         // exp(cm_raw), UNNORMALIZED
__device__ __align__(16) float g_sigctx  [B_*HW_];         // sigmoid(spatial ctx)
__device__ __align__(16) float g_xsum_part[B_*C_*NPART];   // 1 MB
__device__ __align__(16) float g_xw_part  [B_*C_*NPART];   // 1 MB
__device__ __align__(16) float g_xmean[B_*C_];
__device__ __align__(16) float g_xw   [B_*C_];             // unnormalized x@exp(cm)
__device__ __align__(16) float g_a    [B_*INNER_];         // Wsq@xmean (pre-softmax)
__device__ __align__(16) float g_ctx  [B_*INNER_];         // Wcv@(xw/Z)
__device__ __align__(16) float g_z    [B_*C_];             // Wcz@ctx (pre-LN)
__device__ float g_Zc_part[B_*4];                          // exp-sum partials per batch
__device__ float g_weff[B_*C_];
__device__ float g_mask[B_*C_];

// ---------------------------------------------------------------------------
// Reductions
// ---------------------------------------------------------------------------
__device__ __forceinline__ float warpReduceSum(float v) {
    #pragma unroll
    for (int o = 16; o; o >>= 1) v += __shfl_down_sync(0xffffffffu, v, o);
    return v;
}

__device__ __forceinline__ float blockReduceSum(float v) {
    __shared__ float s[17];
    const int lane = threadIdx.x & 31, wid = threadIdx.x >> 5;
    v = warpReduceSum(v);
    if (lane == 0) s[wid] = v;
    __syncthreads();
    if (wid == 0) {
        float t = (lane < (int)(blockDim.x >> 5)) ? s[lane] : 0.0f;
        #pragma unroll
        for (int o = 8; o; o >>= 1) t += __shfl_down_sync(0xffffffffu, t, o);
        if (lane == 0) s[16] = t;
    }
    __syncthreads();
    float r = s[16];
    __syncthreads();
    return r;
}

__device__ __forceinline__ float blockReduceMax(float v) {
    __shared__ float s[17];
    const int lane = threadIdx.x & 31, wid = threadIdx.x >> 5;
    #pragma unroll
    for (int o = 16; o; o >>= 1) v = fmaxf(v, __shfl_down_sync(0xffffffffu, v, o));
    if (lane == 0) s[wid] = v;
    __syncthreads();
    if (wid == 0) {
        float t = (lane < (int)(blockDim.x >> 5)) ? s[lane] : -1e30f;
        #pragma unroll
        for (int o = 8; o; o >>= 1) t = fmaxf(t, __shfl_down_sync(0xffffffffu, t, o));
        if (lane == 0) s[16] = t;
    }
    __syncthreads();
    float r = s[16];
    __syncthreads();
    return r;
}

__device__ __forceinline__ float dot4(float4 a, float4 b) {
    return fmaf(a.x, b.x, fmaf(a.y, b.y, fmaf(a.z, b.z, a.w * b.w)));
}

// ---------------------------------------------------------------------------
// Pass 1: stream x once -> cm_raw partials (per pixel) + xsum partials (per ch)
// grid: (NTILE*NCGRP, B_) = (64, 16) = 1024 CTAs, block: 128
// ---------------------------------------------------------------------------
__global__ __launch_bounds__(NT)
void k_pass1(const float* __restrict__ x, const float* __restrict__ Wcq) {
    const int b    = blockIdx.y;
    const int tile = blockIdx.x >> 3;   // /NCGRP
    const int g    = blockIdx.x & 7;
    const int tid  = threadIdx.x;
    const int lane = tid & 31, warp = tid >> 5;

    __shared__ float s_w[CG];
    if (tid < CG) s_w[tid] = Wcq[g*CG + tid];
    __syncthreads();

    const float4* x4 = reinterpret_cast<const float4*>(x);
    const int pix4 = tile*NT + tid;                    // float4 index within channel
    const int base = (b*C_ + g*CG)*HW4 + pix4;

    float4 acc = make_float4(0.f, 0.f, 0.f, 0.f);
    #pragma unroll 4
    for (int ci = 0; ci < CG; ci++) {
        float4 v = x4[base + ci*HW4];
        float  q = s_w[ci];
        acc.x = fmaf(q, v.x, acc.x);
        acc.y = fmaf(q, v.y, acc.y);
        acc.z = fmaf(q, v.z, acc.z);
        acc.w = fmaf(q, v.w, acc.w);
        // per-channel pixel-sum partial (for xmean)
        float s = (v.x + v.y) + (v.z + v.w);
        s = warpReduceSum(s);
        if (lane == 0)
            g_xsum_part[((b*C_ + g*CG + ci)*NTILE + tile)*NWARP + warp] = s;
    }
    reinterpret_cast<float4*>(g_cm_part)[(b*NCGRP + g)*HW4 + pix4] = acc;
}

// ---------------------------------------------------------------------------
// Red 1 (wide): grid (5, B_), block 256.
//   bx<4 : reduce cm partials -> g_cm = exp(raw), per-CTA expsum -> g_Zc_part
//   bx==4: reduce xsum partials -> g_xmean
// ---------------------------------------------------------------------------
__global__ __launch_bounds__(256)
void k_red1() {
    const int b  = blockIdx.y;
    const int bx = blockIdx.x;
    const int tid = threadIdx.x;

    if (bx < 4) {
        const int pix4 = bx*256 + tid;       // float4 index in [0,HW4)
        const float4* cp = reinterpret_cast<const float4*>(g_cm_part);
        float4 s = make_float4(0.f, 0.f, 0.f, 0.f);
        #pragma unroll
        for (int g = 0; g < NCGRP; g++) {
            float4 v = cp[(b*NCGRP + g)*HW4 + pix4];
            s.x += v.x; s.y += v.y; s.z += v.z; s.w += v.w;
        }
        float4 e;
        e.x = __expf(s.x); e.y = __expf(s.y);
        e.z = __expf(s.z); e.w = __expf(s.w);
        reinterpret_cast<float4*>(g_cm)[b*HW4 + pix4] = e;
        float zs = blockReduceSum((e.x + e.y) + (e.z + e.w));
        if (tid == 0) g_Zc_part[b*4 + bx] = zs;
    } else {
        for (int c = tid; c < C_; c += 256) {
            const float4* p = reinterpret_cast<const float4*>(
                g_xsum_part + (b*C_ + c)*NPART);
            float s = 0.f;
            #pragma unroll
            for (int i = 0; i < NPART/4; i++) {
                float4 v = p[i];
                s += (v.x + v.y) + (v.z + v.w);
            }
            g_xmean[b*C_ + c] = s * (1.0f/(float)HW_);
        }
    }
}

// ---------------------------------------------------------------------------
// GEMM a = Wsq(256x512) @ xmean(512 x 16batches). grid 32, block 256.
// Warp-per-row; all 16 batch vectors in smem; Wsq read ONCE from DRAM.
// ---------------------------------------------------------------------------
__global__ __launch_bounds__(256)
void k_gemm_a(const float* __restrict__ Wsq) {
    const int tid = threadIdx.x;
    const int lane = tid & 31, warp = tid >> 5;
    __shared__ __align__(16) float s_xm[B_*C_];      // 32 KB

    float4* sm4 = reinterpret_cast<float4*>(s_xm);
    const float4* gm4 = reinterpret_cast<const float4*>(g_xmean);
    #pragma unroll
    for (int i = tid; i < B_*C_/4; i += 256) sm4[i] = gm4[i];
    __syncthreads();

    const int row = blockIdx.x*8 + warp;             // [0,256)
    const float4* wr = reinterpret_cast<const float4*>(Wsq + row*C_);
    float acc[B_];
    #pragma unroll
    for (int b = 0; b < B_; b++) acc[b] = 0.f;
    #pragma unroll
    for (int j = 0; j < C_/(4*32); j++) {
        float4 w4 = wr[lane + 32*j];
        #pragma unroll
        for (int b = 0; b < B_; b++)
            acc[b] += dot4(w4, sm4[b*(C_/4) + lane + 32*j]);
    }
    #pragma unroll
    for (int b = 0; b < B_; b++) {
        float r = warpReduceSum(acc[b]);
        if (lane == 0) g_a[b*INNER_ + row] = r;
    }
}

// ---------------------------------------------------------------------------
// weff[b,c] = sum_k softmax(a[b,:])[k] * Wsv[k,c]
// grid (4 c-chunks, B_), block 128. Redundant (cheap) softmax per CTA.
// ---------------------------------------------------------------------------
__global__ __launch_bounds__(128)
void k_weff(const float* __restrict__ Wsv) {
    const int b = blockIdx.y;
    const int cbase = blockIdx.x*128;
    const int tid = threadIdx.x;
    __shared__ __align__(16) float s_avg[INNER_];

    float v0 = g_a[b*INNER_ + tid];
    float v1 = g_a[b*INNER_ + tid + 128];
    float m = blockReduceMax(fmaxf(v0, v1));
    float e0 = __expf(v0 - m), e1 = __expf(v1 - m);
    float s = blockReduceSum(e0 + e1);
    const float inv = 1.0f/s;
    s_avg[tid]       = e0*inv;
    s_avg[tid + 128] = e1*inv;
    __syncthreads();

    float acc = 0.f;
    #pragma unroll 8
    for (int k = 0; k < INNER_; k++)
        acc = fmaf(s_avg[k], Wsv[k*C_ + cbase + tid], acc);
    g_weff[b*C_ + cbase + tid] = acc;
}

// ---------------------------------------------------------------------------
// Pass 2: stream x again -> xw partials (unnormalized, vs exp(cm)) + ctx partials
// ---------------------------------------------------------------------------
__global__ __launch_bounds__(NT)
void k_pass2(const float* __restrict__ x) {
    const int b    = blockIdx.y;
    const int tile = blockIdx.x >> 3;
    const int g    = blockIdx.x & 7;
    const int tid  = threadIdx.x;
    const int lane = tid & 31, warp = tid >> 5;

    __shared__ float s_w[CG];
    if (tid < CG) s_w[tid] = g_weff[b*C_ + g*CG + tid];
    __syncthreads();

    const float4* x4 = reinterpret_cast<const float4*>(x);
    const int pix4 = tile*NT + tid;
    const float4 cm = reinterpret_cast<const float4*>(g_cm)[b*HW4 + pix4];
    const int base = (b*C_ + g*CG)*HW4 + pix4;

    float4 ctx = make_float4(0.f, 0.f, 0.f, 0.f);
    #pragma unroll 4
    for (int ci = 0; ci < CG; ci++) {
        float4 v = x4[base + ci*HW4];
        float  w = s_w[ci];
        ctx.x = fmaf(w, v.x, ctx.x);
        ctx.y = fmaf(w, v.y, ctx.y);
        ctx.z = fmaf(w, v.z, ctx.z);
        ctx.w = fmaf(w, v.w, ctx.w);
        float t = v.x*cm.x + v.y*cm.y + v.z*cm.z + v.w*cm.w;
        t = warpReduceSum(t);
        if (lane == 0)
            g_xw_part[((b*C_ + g*CG + ci)*NTILE + tile)*NWARP + warp] = t;
    }
    reinterpret_cast<float4*>(g_ctx_part)[(b*NCGRP + g)*HW4 + pix4] = ctx;
}

// ---------------------------------------------------------------------------
// Red 2 (wide): grid (5, B_), block 256.
//   bx<4 : reduce ctx partials -> g_sigctx = sigmoid(sum)
//   bx==4: reduce xw partials -> g_xw (unnormalized)
// ---------------------------------------------------------------------------
__global__ __launch_bounds__(256)
void k_red2() {
    const int b  = blockIdx.y;
    const int bx = blockIdx.x;
    const int tid = threadIdx.x;

    if (bx < 4) {
        const int pix4 = bx*256 + tid;
        const float4* cp = reinterpret_cast<const float4*>(g_ctx_part);
        float4 s = make_float4(0.f, 0.f, 0.f, 0.f);
        #pragma unroll
        for (int g = 0; g < NCGRP; g++) {
            float4 v = cp[(b*NCGRP + g)*HW4 + pix4];
            s.x += v.x; s.y += v.y; s.z += v.z; s.w += v.w;
        }
        float4 r;
        r.x = 1.0f/(1.0f + __expf(-s.x));
        r.y = 1.0f/(1.0f + __expf(-s.y));
        r.z = 1.0f/(1.0f + __expf(-s.z));
        r.w = 1.0f/(1.0f + __expf(-s.w));
        reinterpret_cast<float4*>(g_sigctx)[b*HW4 + pix4] = r;
    } else {
        for (int c = tid; c < C_; c += 256) {
            const float4* p = reinterpret_cast<const float4*>(
                g_xw_part + (b*C_ + c)*NPART);
            float s = 0.f;
            #pragma unroll
            for (int i = 0; i < NPART/4; i++) {
                float4 v = p[i];
                s += (v.x + v.y) + (v.z + v.w);
            }
            g_xw[b*C_ + c] = s;
        }
    }
}

// ---------------------------------------------------------------------------
// GEMM ctx = Wcv(256x512) @ (xw/Z)(512 x 16). grid 32, block 256.
// ---------------------------------------------------------------------------
__global__ __launch_bounds__(256)
void k_gemm_ctx(const float* __restrict__ Wcv) {
    const int tid = threadIdx.x;
    const int lane = tid & 31, warp = tid >> 5;
    __shared__ __align__(16) float s_xw[B_*C_];      // 32 KB
    __shared__ float s_invZ[B_];

    if (tid < B_)
        s_invZ[tid] = 1.0f / (g_Zc_part[tid*4+0] + g_Zc_part[tid*4+1] +
                              g_Zc_part[tid*4+2] + g_Zc_part[tid*4+3]);
    __syncthreads();

    float4* sm4 = reinterpret_cast<float4*>(s_xw);
    const float4* gm4 = reinterpret_cast<const float4*>(g_xw);
    #pragma unroll
    for (int i = tid; i < B_*C_/4; i += 256) {
        float4 v = gm4[i];
        float z = s_invZ[i >> 7];       // i*4/512
        v.x *= z; v.y *= z; v.z *= z; v.w *= z;
        sm4[i] = v;
    }
    __syncthreads();

    const int row = blockIdx.x*8 + warp;
    const float4* wr = reinterpret_cast<const float4*>(Wcv + row*C_);
    float acc[B_];
    #pragma unroll
    for (int b = 0; b < B_; b++) acc[b] = 0.f;
    #pragma unroll
    for (int j = 0; j < C_/(4*32); j++) {
        float4 w4 = wr[lane + 32*j];
        #pragma unroll
        for (int b = 0; b < B_; b++)
            acc[b] += dot4(w4, sm4[b*(C_/4) + lane + 32*j]);
    }
    #pragma unroll
    for (int b = 0; b < B_; b++) {
        float r = warpReduceSum(acc[b]);
        if (lane == 0) g_ctx[b*INNER_ + row] = r;
    }
}

// ---------------------------------------------------------------------------
// GEMM z = Wcz(512x256) @ ctx(256 x 16). grid 64, block 256.
// ---------------------------------------------------------------------------
__global__ __launch_bounds__(256)
void k_gemm_z(const float* __restrict__ Wcz) {
    const int tid = threadIdx.x;
    const int lane = tid & 31, warp = tid >> 5;
    __shared__ __align__(16) float s_ctx[B_*INNER_];   // 16 KB

    float4* sm4 = reinterpret_cast<float4*>(s_ctx);
    const float4* gm4 = reinterpret_cast<const float4*>(g_ctx);
    #pragma unroll
    for (int i = tid; i < B_*INNER_/4; i += 256) sm4[i] = gm4[i];
    __syncthreads();

    const int row = blockIdx.x*8 + warp;               // [0,512)
    const float4* wr = reinterpret_cast<const float4*>(Wcz + row*INNER_);
    float acc[B_];
    #pragma unroll
    for (int b = 0; b < B_; b++) acc[b] = 0.f;
    #pragma unroll
    for (int j = 0; j < INNER_/(4*32); j++) {
        float4 w4 = wr[lane + 32*j];
        #pragma unroll
        for (int b = 0; b < B_; b++)
            acc[b] += dot4(w4, sm4[b*(INNER_/4) + lane + 32*j]);
    }
    #pragma unroll
    for (int b = 0; b < B_; b++) {
        float r = warpReduceSum(acc[b]);
        if (lane == 0) g_z[b*C_ + row] = r;
    }
}

// ---------------------------------------------------------------------------
// LayerNorm + sigmoid -> mask. grid B_, block 512.
// ---------------------------------------------------------------------------
__global__ __launch_bounds__(512)
void k_ln(const float* __restrict__ gamma, const float* __restrict__ beta) {
    const int b = blockIdx.x;
    const int tid = threadIdx.x;
    float z = g_z[b*C_ + tid];
    float mu  = blockReduceSum(z) * (1.0f/(float)C_);
    float d   = z - mu;
    float var = blockReduceSum(d*d) * (1.0f/(float)C_);
    float zn  = d * rsqrtf(var + 1e-5f) * gamma[tid] + beta[tid];
    g_mask[b*C_ + tid] = 1.0f/(1.0f + __expf(-zn));
}

// ---------------------------------------------------------------------------
// Final: out = x * (mask[b,c] + sig_ctx[b,n])
// ---------------------------------------------------------------------------
__global__ __launch_bounds__(256)
void k_final(const float* __restrict__ x, float* __restrict__ out) {
    const float4* x4  = reinterpret_cast<const float4*>(x);
    float4*       o4  = reinterpret_cast<float4*>(out);
    const float4* sc4 = reinterpret_cast<const float4*>(g_sigctx);
    const int total4 = B_*C_*HW4;
    for (int i = blockIdx.x*blockDim.x + threadIdx.x; i < total4;
         i += gridDim.x*blockDim.x) {
        const int n4 = i & (HW4 - 1);
        const int bc = i >> 10;          // b*512 + c
        const int b  = bc >> 9;
        const float  m = g_mask[bc];     // warp-uniform -> single sector
        const float4 s = sc4[(b << 10) + n4];
        float4 v = x4[i];
        float4 r;
        r.x = v.x*(m + s.x);
        r.y = v.y*(m + s.y);
        r.z = v.z*(m + s.z);
        r.w = v.w*(m + s.w);
        o4[i] = r;
    }
}

// ---------------------------------------------------------------------------
// Launch
// ---------------------------------------------------------------------------
extern "C" void kernel_launch(void* const* d_in, const int* in_sizes, int n_in,
                              void* d_out, int out_size) {
    const float* x     = (const float*)d_in[0];
    const float* Wsq   = (const float*)d_in[1];
    const float* Wsv   = (const float*)d_in[2];
    const float* Wcq   = (const float*)d_in[3];
    const float* Wcv   = (const float*)d_in[4];
    const float* Wcz   = (const float*)d_in[5];
    const float* gamma = (const float*)d_in[6];
    const float* beta  = (const float*)d_in[7];
    float* out = (float*)d_out;

    dim3 gpass(NTILE*NCGRP, B_);   // 64 x 16 = 1024 CTAs
    dim3 gred(5, B_);              // 80 CTAs
    dim3 gweff(4, B_);             // 64 CTAs
    k_pass1   <<<gpass, NT>>>(x, Wcq);
    k_red1    <<<gred, 256>>>();
    k_gemm_a  <<<32, 256>>>(Wsq);
    k_weff    <<<gweff, 128>>>(Wsv);
    k_pass2   <<<gpass, NT>>>(x);
    k_red2    <<<gred, 256>>>();
    k_gemm_ctx<<<32, 256>>>(Wcv);
    k_gemm_z  <<<64, 256>>>(Wcz);
    k_ln      <<<B_, 512>>>(gamma, beta);
    k_final   <<<8192, 256>>>(x, out);
}

// round 6
// speedup vs baseline: 2.5865x; 1.0891x over previous
#include <cuda_runtime.h>

// Problem constants
#define B_      16
#define C_      512
#define HW_     4096
#define INNER_  256
#define HW4     1024        // HW_/4 (float4 units per channel)

// Pass-kernel tiling
#define NTILE   8           // pixel tiles per batch (512 px each)
#define NCGRP   8           // channel groups per batch (64 ch each)
#define CG      64          // C_ / NCGRP
#define NT      128         // threads per pass CTA
#define NWARP   4           // NT/32
#define NPART   (NTILE*NWARP)  // 32 partials per (b,c)

// weff k-split
#define KCH     8           // k chunks
#define KPER    (INNER_/KCH)   // 32 rows per chunk

// ---------------------------------------------------------------------------
// Scratch (static device globals; fully overwritten every call -> deterministic)
// ---------------------------------------------------------------------------
__device__ __align__(16) float g_cm_part [B_*NCGRP*HW_];   // 2 MB
__device__ __align__(16) float g_ctx_part[B_*NCGRP*HW_];   // 2 MB
__device__ __align__(16) float g_cm      [B_*HW_];         // exp(cm_raw), UNNORMALIZED
__device__ __align__(16) float g_sigctx  [B_*HW_];         // sigmoid(spatial ctx)
__device__ __align__(16) float g_xsum_part[B_*C_*NPART];   // 1 MB
__device__ __align__(16) float g_xw_part  [B_*C_*NPART];   // 1 MB
__device__ __align__(16) float g_xmean[B_*C_];
__device__ __align__(16) float g_xw   [B_*C_];             // unnormalized x@exp(cm)
__device__ __align__(16) float g_a    [B_*INNER_];         // Wsq@xmean (pre-softmax)
__device__ __align__(16) float g_ctx  [B_*INNER_];         // Wcv@(xw/Z)
__device__ __align__(16) float g_z    [B_*C_];             // Wcz@ctx (pre-LN)
__device__ __align__(16) float g_weff_part[KCH*B_*C_];     // 64 KB k-chunk partials
__device__ float g_Zc_part[B_*4];                          // exp-sum partials per batch
__device__ float g_mask[B_*C_];

// ---------------------------------------------------------------------------
// Reductions
// ---------------------------------------------------------------------------
__device__ __forceinline__ float warpReduceSum(float v) {
    #pragma unroll
    for (int o = 16; o; o >>= 1) v += __shfl_down_sync(0xffffffffu, v, o);
    return v;
}

__device__ __forceinline__ float blockReduceSum(float v) {
    __shared__ float s[17];
    const int lane = threadIdx.x & 31, wid = threadIdx.x >> 5;
    v = warpReduceSum(v);
    if (lane == 0) s[wid] = v;
    __syncthreads();
    if (wid == 0) {
        float t = (lane < (int)(blockDim.x >> 5)) ? s[lane] : 0.0f;
        #pragma unroll
        for (int o = 8; o; o >>= 1) t += __shfl_down_sync(0xffffffffu, t, o);
        if (lane == 0) s[16] = t;
    }
    __syncthreads();
    float r = s[16];
    __syncthreads();
    return r;
}

__device__ __forceinline__ float blockReduceMax(float v) {
    __shared__ float s[17];
    const int lane = threadIdx.x & 31, wid = threadIdx.x >> 5;
    #pragma unroll
    for (int o = 16; o; o >>= 1) v = fmaxf(v, __shfl_down_sync(0xffffffffu, v, o));
    if (lane == 0) s[wid] = v;
    __syncthreads();
    if (wid == 0) {
        float t = (lane < (int)(blockDim.x >> 5)) ? s[lane] : -1e30f;
        #pragma unroll
        for (int o = 8; o; o >>= 1) t = fmaxf(t, __shfl_down_sync(0xffffffffu, t, o));
        if (lane == 0) s[16] = t;
    }
    __syncthreads();
    float r = s[16];
    __syncthreads();
    return r;
}

__device__ __forceinline__ float dot4(float4 a, float4 b) {
    return fmaf(a.x, b.x, fmaf(a.y, b.y, fmaf(a.z, b.z, a.w * b.w)));
}

// ---------------------------------------------------------------------------
// Pass 1: stream x once -> cm_raw partials (per pixel) + xsum partials (per ch)
// grid: (NTILE*NCGRP, B_) = (64, 16) = 1024 CTAs, block: 128
// ---------------------------------------------------------------------------
__global__ __launch_bounds__(NT)
void k_pass1(const float* __restrict__ x, const float* __restrict__ Wcq) {
    const int b    = blockIdx.y;
    const int tile = blockIdx.x >> 3;   // /NCGRP
    const int g    = blockIdx.x & 7;
    const int tid  = threadIdx.x;
    const int lane = tid & 31, warp = tid >> 5;

    __shared__ float s_w[CG];
    if (tid < CG) s_w[tid] = Wcq[g*CG + tid];
    __syncthreads();

    const float4* x4 = reinterpret_cast<const float4*>(x);
    const int pix4 = tile*NT + tid;                    // float4 index within channel
    const int base = (b*C_ + g*CG)*HW4 + pix4;

    float4 acc = make_float4(0.f, 0.f, 0.f, 0.f);
    #pragma unroll 4
    for (int ci = 0; ci < CG; ci++) {
        float4 v = x4[base + ci*HW4];
        float  q = s_w[ci];
        acc.x = fmaf(q, v.x, acc.x);
        acc.y = fmaf(q, v.y, acc.y);
        acc.z = fmaf(q, v.z, acc.z);
        acc.w = fmaf(q, v.w, acc.w);
        // per-channel pixel-sum partial (for xmean)
        float s = (v.x + v.y) + (v.z + v.w);
        s = warpReduceSum(s);
        if (lane == 0)
            g_xsum_part[((b*C_ + g*CG + ci)*NTILE + tile)*NWARP + warp] = s;
    }
    reinterpret_cast<float4*>(g_cm_part)[(b*NCGRP + g)*HW4 + pix4] = acc;
}

// ---------------------------------------------------------------------------
// Red 1 (wide): grid (5, B_), block 256.
//   bx<4 : reduce cm partials -> g_cm = exp(raw), per-CTA expsum -> g_Zc_part
//   bx==4: reduce xsum partials -> g_xmean
// ---------------------------------------------------------------------------
__global__ __launch_bounds__(256)
void k_red1() {
    const int b  = blockIdx.y;
    const int bx = blockIdx.x;
    const int tid = threadIdx.x;

    if (bx < 4) {
        const int pix4 = bx*256 + tid;       // float4 index in [0,HW4)
        const float4* cp = reinterpret_cast<const float4*>(g_cm_part);
        float4 s = make_float4(0.f, 0.f, 0.f, 0.f);
        #pragma unroll
        for (int g = 0; g < NCGRP; g++) {
            float4 v = cp[(b*NCGRP + g)*HW4 + pix4];
            s.x += v.x; s.y += v.y; s.z += v.z; s.w += v.w;
        }
        float4 e;
        e.x = __expf(s.x); e.y = __expf(s.y);
        e.z = __expf(s.z); e.w = __expf(s.w);
        reinterpret_cast<float4*>(g_cm)[b*HW4 + pix4] = e;
        float zs = blockReduceSum((e.x + e.y) + (e.z + e.w));
        if (tid == 0) g_Zc_part[b*4 + bx] = zs;
    } else {
        for (int c = tid; c < C_; c += 256) {
            const float4* p = reinterpret_cast<const float4*>(
                g_xsum_part + (b*C_ + c)*NPART);
            float s = 0.f;
            #pragma unroll
            for (int i = 0; i < NPART/4; i++) {
                float4 v = p[i];
                s += (v.x + v.y) + (v.z + v.w);
            }
            g_xmean[b*C_ + c] = s * (1.0f/(float)HW_);
        }
    }
}

// ---------------------------------------------------------------------------
// GEMM a = Wsq(256x512) @ xmean(512 x 16batches). grid 32, block 256.
// Warp-per-row; all 16 batch vectors in smem; Wsq read ONCE from DRAM.
// ---------------------------------------------------------------------------
__global__ __launch_bounds__(256)
void k_gemm_a(const float* __restrict__ Wsq) {
    const int tid = threadIdx.x;
    const int lane = tid & 31, warp = tid >> 5;
    __shared__ __align__(16) float s_xm[B_*C_];      // 32 KB

    float4* sm4 = reinterpret_cast<float4*>(s_xm);
    const float4* gm4 = reinterpret_cast<const float4*>(g_xmean);
    #pragma unroll
    for (int i = tid; i < B_*C_/4; i += 256) sm4[i] = gm4[i];
    __syncthreads();

    const int row = blockIdx.x*8 + warp;             // [0,256)
    const float4* wr = reinterpret_cast<const float4*>(Wsq + row*C_);
    float acc[B_];
    #pragma unroll
    for (int b = 0; b < B_; b++) acc[b] = 0.f;
    #pragma unroll
    for (int j = 0; j < C_/(4*32); j++) {
        float4 w4 = wr[lane + 32*j];
        #pragma unroll
        for (int b = 0; b < B_; b++)
            acc[b] += dot4(w4, sm4[b*(C_/4) + lane + 32*j]);
    }
    #pragma unroll
    for (int b = 0; b < B_; b++) {
        float r = warpReduceSum(acc[b]);
        if (lane == 0) g_a[b*INNER_ + row] = r;
    }
}

// ---------------------------------------------------------------------------
// weff partials: grid (KCH, B_) = 128 CTAs, block 128.
// Each CTA: redundant softmax over a[b,:] (cheap), then float4-per-thread
// accumulation over its 32 k-rows of Wsv (row = 128 thr x 16B, coalesced).
// ---------------------------------------------------------------------------
__global__ __launch_bounds__(128)
void k_weff(const float* __restrict__ Wsv) {
    const int kc = blockIdx.x;
    const int b  = blockIdx.y;
    const int tid = threadIdx.x;
    __shared__ __align__(16) float s_avg[KPER];

    // softmax over inner=256 (2 values per thread), keep only our k-chunk
    float v0 = g_a[b*INNER_ + tid];
    float v1 = g_a[b*INNER_ + tid + 128];
    float m  = blockReduceMax(fmaxf(v0, v1));
    float e0 = __expf(v0 - m), e1 = __expf(v1 - m);
    float s  = blockReduceSum(e0 + e1);
    const float inv = 1.0f/s;
    // our chunk rows: [kc*KPER, kc*KPER+KPER)
    if (tid >= kc*KPER && tid < kc*KPER + KPER)          s_avg[tid - kc*KPER] = e0*inv;
    int t1 = tid + 128;
    if (t1 >= kc*KPER && t1 < kc*KPER + KPER)            s_avg[t1 - kc*KPER] = e1*inv;
    __syncthreads();

    const float4* w4 = reinterpret_cast<const float4*>(Wsv);
    float4 acc = make_float4(0.f, 0.f, 0.f, 0.f);
    #pragma unroll 8
    for (int k = 0; k < KPER; k++) {
        float4 w = w4[(kc*KPER + k)*(C_/4) + tid];       // coalesced full row
        float  a = s_avg[k];
        acc.x = fmaf(a, w.x, acc.x);
        acc.y = fmaf(a, w.y, acc.y);
        acc.z = fmaf(a, w.z, acc.z);
        acc.w = fmaf(a, w.w, acc.w);
    }
    reinterpret_cast<float4*>(g_weff_part)[(kc*B_ + b)*(C_/4) + tid] = acc;
}

// ---------------------------------------------------------------------------
// Pass 2: stream x again -> xw partials (unnormalized, vs exp(cm)) + ctx partials
// ---------------------------------------------------------------------------
__global__ __launch_bounds__(NT)
void k_pass2(const float* __restrict__ x) {
    const int b    = blockIdx.y;
    const int tile = blockIdx.x >> 3;
    const int g    = blockIdx.x & 7;
    const int tid  = threadIdx.x;
    const int lane = tid & 31, warp = tid >> 5;

    __shared__ float s_w[CG];
    if (tid < CG) {
        float s = 0.f;
        #pragma unroll
        for (int p = 0; p < KCH; p++)
            s += g_weff_part[(p*B_ + b)*C_ + g*CG + tid];
        s_w[tid] = s;
    }
    __syncthreads();

    const float4* x4 = reinterpret_cast<const float4*>(x);
    const int pix4 = tile*NT + tid;
    const float4 cm = reinterpret_cast<const float4*>(g_cm)[b*HW4 + pix4];
    const int base = (b*C_ + g*CG)*HW4 + pix4;

    float4 ctx = make_float4(0.f, 0.f, 0.f, 0.f);
    #pragma unroll 4
    for (int ci = 0; ci < CG; ci++) {
        float4 v = x4[base + ci*HW4];
        float  w = s_w[ci];
        ctx.x = fmaf(w, v.x, ctx.x);
        ctx.y = fmaf(w, v.y, ctx.y);
        ctx.z = fmaf(w, v.z, ctx.z);
        ctx.w = fmaf(w, v.w, ctx.w);
        float t = v.x*cm.x + v.y*cm.y + v.z*cm.z + v.w*cm.w;
        t = warpReduceSum(t);
        if (lane == 0)
            g_xw_part[((b*C_ + g*CG + ci)*NTILE + tile)*NWARP + warp] = t;
    }
    reinterpret_cast<float4*>(g_ctx_part)[(b*NCGRP + g)*HW4 + pix4] = ctx;
}

// ---------------------------------------------------------------------------
// Red 2 (wide): grid (5, B_), block 256.
//   bx<4 : reduce ctx partials -> g_sigctx = sigmoid(sum)
//   bx==4: reduce xw partials -> g_xw (unnormalized)
// ---------------------------------------------------------------------------
__global__ __launch_bounds__(256)
void k_red2() {
    const int b  = blockIdx.y;
    const int bx = blockIdx.x;
    const int tid = threadIdx.x;

    if (bx < 4) {
        const int pix4 = bx*256 + tid;
        const float4* cp = reinterpret_cast<const float4*>(g_ctx_part);
        float4 s = make_float4(0.f, 0.f, 0.f, 0.f);
        #pragma unroll
        for (int g = 0; g < NCGRP; g++) {
            float4 v = cp[(b*NCGRP + g)*HW4 + pix4];
            s.x += v.x; s.y += v.y; s.z += v.z; s.w += v.w;
        }
        float4 r;
        r.x = 1.0f/(1.0f + __expf(-s.x));
        r.y = 1.0f/(1.0f + __expf(-s.y));
        r.z = 1.0f/(1.0f + __expf(-s.z));
        r.w = 1.0f/(1.0f + __expf(-s.w));
        reinterpret_cast<float4*>(g_sigctx)[b*HW4 + pix4] = r;
    } else {
        for (int c = tid; c < C_; c += 256) {
            const float4* p = reinterpret_cast<const float4*>(
                g_xw_part + (b*C_ + c)*NPART);
            float s = 0.f;
            #pragma unroll
            for (int i = 0; i < NPART/4; i++) {
                float4 v = p[i];
                s += (v.x + v.y) + (v.z + v.w);
            }
            g_xw[b*C_ + c] = s;
        }
    }
}

// ---------------------------------------------------------------------------
// GEMM ctx = Wcv(256x512) @ (xw/Z)(512 x 16). grid 32, block 256.
// ---------------------------------------------------------------------------
__global__ __launch_bounds__(256)
void k_gemm_ctx(const float* __restrict__ Wcv) {
    const int tid = threadIdx.x;
    const int lane = tid & 31, warp = tid >> 5;
    __shared__ __align__(16) float s_xw[B_*C_];      // 32 KB
    __shared__ float s_invZ[B_];

    if (tid < B_)
        s_invZ[tid] = 1.0f / (g_Zc_part[tid*4+0] + g_Zc_part[tid*4+1] +
                              g_Zc_part[tid*4+2] + g_Zc_part[tid*4+3]);
    __syncthreads();

    float4* sm4 = reinterpret_cast<float4*>(s_xw);
    const float4* gm4 = reinterpret_cast<const float4*>(g_xw);
    #pragma unroll
    for (int i = tid; i < B_*C_/4; i += 256) {
        float4 v = gm4[i];
        float z = s_invZ[i >> 7];       // i*4/512
        v.x *= z; v.y *= z; v.z *= z; v.w *= z;
        sm4[i] = v;
    }
    __syncthreads();

    const int row = blockIdx.x*8 + warp;
    const float4* wr = reinterpret_cast<const float4*>(Wcv + row*C_);
    float acc[B_];
    #pragma unroll
    for (int b = 0; b < B_; b++) acc[b] = 0.f;
    #pragma unroll
    for (int j = 0; j < C_/(4*32); j++) {
        float4 w4 = wr[lane + 32*j];
        #pragma unroll
        for (int b = 0; b < B_; b++)
            acc[b] += dot4(w4, sm4[b*(C_/4) + lane + 32*j]);
    }
    #pragma unroll
    for (int b = 0; b < B_; b++) {
        float r = warpReduceSum(acc[b]);
        if (lane == 0) g_ctx[b*INNER_ + row] = r;
    }
}

// ---------------------------------------------------------------------------
// GEMM z = Wcz(512x256) @ ctx(256 x 16). grid 64, block 256.
// ---------------------------------------------------------------------------
__global__ __launch_bounds__(256)
void k_gemm_z(const float* __restrict__ Wcz) {
    const int tid = threadIdx.x;
    const int lane = tid & 31, warp = tid >> 5;
    __shared__ __align__(16) float s_ctx[B_*INNER_];   // 16 KB

    float4* sm4 = reinterpret_cast<float4*>(s_ctx);
    const float4* gm4 = reinterpret_cast<const float4*>(g_ctx);
    #pragma unroll
    for (int i = tid; i < B_*INNER_/4; i += 256) sm4[i] = gm4[i];
    __syncthreads();

    const int row = blockIdx.x*8 + warp;               // [0,512)
    const float4* wr = reinterpret_cast<const float4*>(Wcz + row*INNER_);
    float acc[B_];
    #pragma unroll
    for (int b = 0; b < B_; b++) acc[b] = 0.f;
    #pragma unroll
    for (int j = 0; j < INNER_/(4*32); j++) {
        float4 w4 = wr[lane + 32*j];
        #pragma unroll
        for (int b = 0; b < B_; b++)
            acc[b] += dot4(w4, sm4[b*(INNER_/4) + lane + 32*j]);
    }
    #pragma unroll
    for (int b = 0; b < B_; b++) {
        float r = warpReduceSum(acc[b]);
        if (lane == 0) g_z[b*C_ + row] = r;
    }
}

// ---------------------------------------------------------------------------
// LayerNorm + sigmoid -> mask. grid B_, block 512.
// ---------------------------------------------------------------------------
__global__ __launch_bounds__(512)
void k_ln(const float* __restrict__ gamma, const float* __restrict__ beta) {
    const int b = blockIdx.x;
    const int tid = threadIdx.x;
    float z = g_z[b*C_ + tid];
    float mu  = blockReduceSum(z) * (1.0f/(float)C_);
    float d   = z - mu;
    float var = blockReduceSum(d*d) * (1.0f/(float)C_);
    float zn  = d * rsqrtf(var + 1e-5f) * gamma[tid] + beta[tid];
    g_mask[b*C_ + tid] = 1.0f/(1.0f + __expf(-zn));
}

// ---------------------------------------------------------------------------
// Final: out = x * (mask[b,c] + sig_ctx[b,n])
// ---------------------------------------------------------------------------
__global__ __launch_bounds__(256)
void k_final(const float* __restrict__ x, float* __restrict__ out) {
    const float4* x4  = reinterpret_cast<const float4*>(x);
    float4*       o4  = reinterpret_cast<float4*>(out);
    const float4* sc4 = reinterpret_cast<const float4*>(g_sigctx);
    const int total4 = B_*C_*HW4;
    for (int i = blockIdx.x*blockDim.x + threadIdx.x; i < total4;
         i += gridDim.x*blockDim.x) {
        const int n4 = i & (HW4 - 1);
        const int bc = i >> 10;          // b*512 + c
        const int b  = bc >> 9;
        const float  m = g_mask[bc];     // warp-uniform -> single sector
        const float4 s = sc4[(b << 10) + n4];
        float4 v = x4[i];
        float4 r;
        r.x = v.x*(m + s.x);
        r.y = v.y*(m + s.y);
        r.z = v.z*(m + s.z);
        r.w = v.w*(m + s.w);
        o4[i] = r;
    }
}

// ---------------------------------------------------------------------------
// Launch
// ---------------------------------------------------------------------------
extern "C" void kernel_launch(void* const* d_in, const int* in_sizes, int n_in,
                              void* d_out, int out_size) {
    const float* x     = (const float*)d_in[0];
    const float* Wsq   = (const float*)d_in[1];
    const float* Wsv   = (const float*)d_in[2];
    const float* Wcq   = (const float*)d_in[3];
    const float* Wcv   = (const float*)d_in[4];
    const float* Wcz   = (const float*)d_in[5];
    const float* gamma = (const float*)d_in[6];
    const float* beta  = (const float*)d_in[7];
    float* out = (float*)d_out;

    dim3 gpass(NTILE*NCGRP, B_);   // 64 x 16 = 1024 CTAs
    dim3 gred(5, B_);              // 80 CTAs
    dim3 gweff(KCH, B_);           // 128 CTAs
    k_pass1   <<<gpass, NT>>>(x, Wcq);
    k_red1    <<<gred, 256>>>();
    k_gemm_a  <<<32, 256>>>(Wsq);
    k_weff    <<<gweff, 128>>>(Wsv);
    k_pass2   <<<gpass, NT>>>(x);
    k_red2    <<<gred, 256>>>();
    k_gemm_ctx<<<32, 256>>>(Wcv);
    k_gemm_z  <<<64, 256>>>(Wcz);
    k_ln      <<<B_, 512>>>(gamma, beta);
    k_final   <<<8192, 256>>>(x, out);
}

// round 7
// speedup vs baseline: 2.7923x; 1.0796x over previous
#include <cuda_runtime.h>

// Problem constants
#define B_      16
#define C_      512
#define HW_     4096
#define INNER_  256
#define HW4     1024        // HW_/4 (float4 units per channel)

// Pass-kernel tiling
#define NTILE   8           // pixel tiles per batch (512 px each)
#define NCGRP   16          // channel groups per batch (32 ch each)
#define CG      32          // C_ / NCGRP
#define NT      128         // threads per pass CTA
#define NWARP   4           // NT/32
#define NPART   (NTILE*NWARP)  // 32 partials per (b,c)

// weff k-split
#define KCH     16          // k chunks
#define KPER    (INNER_/KCH)   // 16 rows per chunk

// ---------------------------------------------------------------------------
// Scratch (static device globals; fully overwritten every call -> deterministic)
// ---------------------------------------------------------------------------
__device__ __align__(16) float g_cm_part [B_*NCGRP*HW_];   // 4 MB
__device__ __align__(16) float g_ctx_part[B_*NCGRP*HW_];   // 4 MB
__device__ __align__(16) float g_cm      [B_*HW_];         // exp(cm_raw), UNNORMALIZED
__device__ __align__(16) float g_sigctx  [B_*HW_];         // sigmoid(spatial ctx)
__device__ __align__(16) float g_xsum_part[B_*C_*NPART];   // 1 MB
__device__ __align__(16) float g_xw_part  [B_*C_*NPART];   // 1 MB
__device__ __align__(16) float g_xmean[B_*C_];
__device__ __align__(16) float g_xw   [B_*C_];             // unnormalized x@exp(cm)
__device__ __align__(16) float g_a    [B_*INNER_];         // Wsq@xmean (pre-softmax)
__device__ __align__(16) float g_ctx  [B_*INNER_];         // Wcv@(xw/Z)
__device__ __align__(16) float g_z    [B_*C_];             // Wcz@ctx (pre-LN)
__device__ __align__(16) float g_weff_part[KCH*B_*C_];     // k-chunk partials
__device__ float g_Zc_part[B_*4];                          // exp-sum partials per batch
__device__ float g_mask[B_*C_];

// ---------------------------------------------------------------------------
// Reductions
// ---------------------------------------------------------------------------
__device__ __forceinline__ float warpReduceSum(float v) {
    #pragma unroll
    for (int o = 16; o; o >>= 1) v += __shfl_down_sync(0xffffffffu, v, o);
    return v;
}

__device__ __forceinline__ float blockReduceSum(float v) {
    __shared__ float s[17];
    const int lane = threadIdx.x & 31, wid = threadIdx.x >> 5;
    v = warpReduceSum(v);
    if (lane == 0) s[wid] = v;
    __syncthreads();
    if (wid == 0) {
        float t = (lane < (int)(blockDim.x >> 5)) ? s[lane] : 0.0f;
        #pragma unroll
        for (int o = 8; o; o >>= 1) t += __shfl_down_sync(0xffffffffu, t, o);
        if (lane == 0) s[16] = t;
    }
    __syncthreads();
    float r = s[16];
    __syncthreads();
    return r;
}

__device__ __forceinline__ float blockReduceMax(float v) {
    __shared__ float s[17];
    const int lane = threadIdx.x & 31, wid = threadIdx.x >> 5;
    #pragma unroll
    for (int o = 16; o; o >>= 1) v = fmaxf(v, __shfl_down_sync(0xffffffffu, v, o));
    if (lane == 0) s[wid] = v;
    __syncthreads();
    if (wid == 0) {
        float t = (lane < (int)(blockDim.x >> 5)) ? s[lane] : -1e30f;
        #pragma unroll
        for (int o = 8; o; o >>= 1) t = fmaxf(t, __shfl_down_sync(0xffffffffu, t, o));
        if (lane == 0) s[16] = t;
    }
    __syncthreads();
    float r = s[16];
    __syncthreads();
    return r;
}

__device__ __forceinline__ float dot4(float4 a, float4 b) {
    return fmaf(a.x, b.x, fmaf(a.y, b.y, fmaf(a.z, b.z, a.w * b.w)));
}

// ---------------------------------------------------------------------------
// Pass 1: stream x once -> cm_raw partials (per pixel) + xsum partials (per ch)
// grid: (NTILE*NCGRP, B_) = (128, 16) = 2048 CTAs, block: 128
// ---------------------------------------------------------------------------
__global__ __launch_bounds__(NT)
void k_pass1(const float* __restrict__ x, const float* __restrict__ Wcq) {
    const int b    = blockIdx.y;
    const int tile = blockIdx.x >> 4;   // /NCGRP
    const int g    = blockIdx.x & 15;
    const int tid  = threadIdx.x;
    const int lane = tid & 31, warp = tid >> 5;

    __shared__ float s_w[CG];
    if (tid < CG) s_w[tid] = Wcq[g*CG + tid];
    __syncthreads();

    const float4* x4 = reinterpret_cast<const float4*>(x);
    const int pix4 = tile*NT + tid;                    // float4 index within channel
    const int base = (b*C_ + g*CG)*HW4 + pix4;

    float4 acc = make_float4(0.f, 0.f, 0.f, 0.f);
    #pragma unroll 4
    for (int ci = 0; ci < CG; ci++) {
        float4 v = x4[base + ci*HW4];
        float  q = s_w[ci];
        acc.x = fmaf(q, v.x, acc.x);
        acc.y = fmaf(q, v.y, acc.y);
        acc.z = fmaf(q, v.z, acc.z);
        acc.w = fmaf(q, v.w, acc.w);
        // per-channel pixel-sum partial (for xmean)
        float s = (v.x + v.y) + (v.z + v.w);
        s = warpReduceSum(s);
        if (lane == 0)
            g_xsum_part[((b*C_ + g*CG + ci)*NTILE + tile)*NWARP + warp] = s;
    }
    reinterpret_cast<float4*>(g_cm_part)[(b*NCGRP + g)*HW4 + pix4] = acc;
}

// ---------------------------------------------------------------------------
// Red 1 (wide): grid (5, B_), block 256.
//   bx<4 : reduce cm partials -> g_cm = exp(raw), per-CTA expsum -> g_Zc_part
//   bx==4: reduce xsum partials -> g_xmean
// ---------------------------------------------------------------------------
__global__ __launch_bounds__(256)
void k_red1() {
    const int b  = blockIdx.y;
    const int bx = blockIdx.x;
    const int tid = threadIdx.x;

    if (bx < 4) {
        const int pix4 = bx*256 + tid;       // float4 index in [0,HW4)
        const float4* cp = reinterpret_cast<const float4*>(g_cm_part);
        float4 s = make_float4(0.f, 0.f, 0.f, 0.f);
        #pragma unroll
        for (int g = 0; g < NCGRP; g++) {
            float4 v = cp[(b*NCGRP + g)*HW4 + pix4];
            s.x += v.x; s.y += v.y; s.z += v.z; s.w += v.w;
        }
        float4 e;
        e.x = __expf(s.x); e.y = __expf(s.y);
        e.z = __expf(s.z); e.w = __expf(s.w);
        reinterpret_cast<float4*>(g_cm)[b*HW4 + pix4] = e;
        float zs = blockReduceSum((e.x + e.y) + (e.z + e.w));
        if (tid == 0) g_Zc_part[b*4 + bx] = zs;
    } else {
        for (int c = tid; c < C_; c += 256) {
            const float4* p = reinterpret_cast<const float4*>(
                g_xsum_part + (b*C_ + c)*NPART);
            float s = 0.f;
            #pragma unroll
            for (int i = 0; i < NPART/4; i++) {
                float4 v = p[i];
                s += (v.x + v.y) + (v.z + v.w);
            }
            g_xmean[b*C_ + c] = s * (1.0f/(float)HW_);
        }
    }
}

// ---------------------------------------------------------------------------
// GEMM a = Wsq(256x512) @ xmean(512 x 16batches). grid 32, block 256.
// Warp-per-row; all 16 batch vectors in smem; Wsq read ONCE from DRAM.
// ---------------------------------------------------------------------------
__global__ __launch_bounds__(256)
void k_gemm_a(const float* __restrict__ Wsq) {
    const int tid = threadIdx.x;
    const int lane = tid & 31, warp = tid >> 5;
    __shared__ __align__(16) float s_xm[B_*C_];      // 32 KB

    float4* sm4 = reinterpret_cast<float4*>(s_xm);
    const float4* gm4 = reinterpret_cast<const float4*>(g_xmean);
    #pragma unroll
    for (int i = tid; i < B_*C_/4; i += 256) sm4[i] = gm4[i];
    __syncthreads();

    const int row = blockIdx.x*8 + warp;             // [0,256)
    const float4* wr = reinterpret_cast<const float4*>(Wsq + row*C_);
    float acc[B_];
    #pragma unroll
    for (int b = 0; b < B_; b++) acc[b] = 0.f;
    #pragma unroll
    for (int j = 0; j < C_/(4*32); j++) {
        float4 w4 = wr[lane + 32*j];
        #pragma unroll
        for (int b = 0; b < B_; b++)
            acc[b] += dot4(w4, sm4[b*(C_/4) + lane + 32*j]);
    }
    #pragma unroll
    for (int b = 0; b < B_; b++) {
        float r = warpReduceSum(acc[b]);
        if (lane == 0) g_a[b*INNER_ + row] = r;
    }
}

// ---------------------------------------------------------------------------
// weff partials: grid (KCH, B_) = 256 CTAs, block 128.
// Each CTA: redundant softmax over a[b,:] (cheap), then float4-per-thread
// accumulation over its 16 k-rows of Wsv (row = 128 thr x 16B, coalesced).
// ---------------------------------------------------------------------------
__global__ __launch_bounds__(128)
void k_weff(const float* __restrict__ Wsv) {
    const int kc = blockIdx.x;
    const int b  = blockIdx.y;
    const int tid = threadIdx.x;
    __shared__ __align__(16) float s_avg[KPER];

    // softmax over inner=256 (2 values per thread), keep only our k-chunk
    float v0 = g_a[b*INNER_ + tid];
    float v1 = g_a[b*INNER_ + tid + 128];
    float m  = blockReduceMax(fmaxf(v0, v1));
    float e0 = __expf(v0 - m), e1 = __expf(v1 - m);
    float s  = blockReduceSum(e0 + e1);
    const float inv = 1.0f/s;
    // our chunk rows: [kc*KPER, kc*KPER+KPER)
    if (tid >= kc*KPER && tid < kc*KPER + KPER)          s_avg[tid - kc*KPER] = e0*inv;
    int t1 = tid + 128;
    if (t1 >= kc*KPER && t1 < kc*KPER + KPER)            s_avg[t1 - kc*KPER] = e1*inv;
    __syncthreads();

    const float4* w4 = reinterpret_cast<const float4*>(Wsv);
    float4 acc = make_float4(0.f, 0.f, 0.f, 0.f);
    #pragma unroll
    for (int k = 0; k < KPER; k++) {
        float4 w = w4[(kc*KPER + k)*(C_/4) + tid];       // coalesced full row
        float  a = s_avg[k];
        acc.x = fmaf(a, w.x, acc.x);
        acc.y = fmaf(a, w.y, acc.y);
        acc.z = fmaf(a, w.z, acc.z);
        acc.w = fmaf(a, w.w, acc.w);
    }
    reinterpret_cast<float4*>(g_weff_part)[(kc*B_ + b)*(C_/4) + tid] = acc;
}

// ---------------------------------------------------------------------------
// Pass 2: stream x again -> xw partials (unnormalized, vs exp(cm)) + ctx partials
// ---------------------------------------------------------------------------
__global__ __launch_bounds__(NT)
void k_pass2(const float* __restrict__ x) {
    const int b    = blockIdx.y;
    const int tile = blockIdx.x >> 4;
    const int g    = blockIdx.x & 15;
    const int tid  = threadIdx.x;
    const int lane = tid & 31, warp = tid >> 5;

    __shared__ float s_w[CG];
    if (tid < CG) {
        float s = 0.f;
        #pragma unroll
        for (int p = 0; p < KCH; p++)
            s += g_weff_part[(p*B_ + b)*C_ + g*CG + tid];
        s_w[tid] = s;
    }
    __syncthreads();

    const float4* x4 = reinterpret_cast<const float4*>(x);
    const int pix4 = tile*NT + tid;
    const float4 cm = reinterpret_cast<const float4*>(g_cm)[b*HW4 + pix4];
    const int base = (b*C_ + g*CG)*HW4 + pix4;

    float4 ctx = make_float4(0.f, 0.f, 0.f, 0.f);
    #pragma unroll 4
    for (int ci = 0; ci < CG; ci++) {
        float4 v = x4[base + ci*HW4];
        float  w = s_w[ci];
        ctx.x = fmaf(w, v.x, ctx.x);
        ctx.y = fmaf(w, v.y, ctx.y);
        ctx.z = fmaf(w, v.z, ctx.z);
        ctx.w = fmaf(w, v.w, ctx.w);
        float t = v.x*cm.x + v.y*cm.y + v.z*cm.z + v.w*cm.w;
        t = warpReduceSum(t);
        if (lane == 0)
            g_xw_part[((b*C_ + g*CG + ci)*NTILE + tile)*NWARP + warp] = t;
    }
    reinterpret_cast<float4*>(g_ctx_part)[(b*NCGRP + g)*HW4 + pix4] = ctx;
}

// ---------------------------------------------------------------------------
// Red 2 (wide): grid (5, B_), block 256.
//   bx<4 : reduce ctx partials -> g_sigctx = sigmoid(sum)
//   bx==4: reduce xw partials -> g_xw (unnormalized)
// ---------------------------------------------------------------------------
__global__ __launch_bounds__(256)
void k_red2() {
    const int b  = blockIdx.y;
    const int bx = blockIdx.x;
    const int tid = threadIdx.x;

    if (bx < 4) {
        const int pix4 = bx*256 + tid;
        const float4* cp = reinterpret_cast<const float4*>(g_ctx_part);
        float4 s = make_float4(0.f, 0.f, 0.f, 0.f);
        #pragma unroll
        for (int g = 0; g < NCGRP; g++) {
            float4 v = cp[(b*NCGRP + g)*HW4 + pix4];
            s.x += v.x; s.y += v.y; s.z += v.z; s.w += v.w;
        }
        float4 r;
        r.x = 1.0f/(1.0f + __expf(-s.x));
        r.y = 1.0f/(1.0f + __expf(-s.y));
        r.z = 1.0f/(1.0f + __expf(-s.z));
        r.w = 1.0f/(1.0f + __expf(-s.w));
        reinterpret_cast<float4*>(g_sigctx)[b*HW4 + pix4] = r;
    } else {
        for (int c = tid; c < C_; c += 256) {
            const float4* p = reinterpret_cast<const float4*>(
                g_xw_part + (b*C_ + c)*NPART);
            float s = 0.f;
            #pragma unroll
            for (int i = 0; i < NPART/4; i++) {
                float4 v = p[i];
                s += (v.x + v.y) + (v.z + v.w);
            }
            g_xw[b*C_ + c] = s;
        }
    }
}

// ---------------------------------------------------------------------------
// GEMM ctx = Wcv(256x512) @ (xw/Z)(512 x 16). grid 32, block 256.
// ---------------------------------------------------------------------------
__global__ __launch_bounds__(256)
void k_gemm_ctx(const float* __restrict__ Wcv) {
    const int tid = threadIdx.x;
    const int lane = tid & 31, warp = tid >> 5;
    __shared__ __align__(16) float s_xw[B_*C_];      // 32 KB
    __shared__ float s_invZ[B_];

    if (tid < B_)
        s_invZ[tid] = 1.0f / (g_Zc_part[tid*4+0] + g_Zc_part[tid*4+1] +
                              g_Zc_part[tid*4+2] + g_Zc_part[tid*4+3]);
    __syncthreads();

    float4* sm4 = reinterpret_cast<float4*>(s_xw);
    const float4* gm4 = reinterpret_cast<const float4*>(g_xw);
    #pragma unroll
    for (int i = tid; i < B_*C_/4; i += 256) {
        float4 v = gm4[i];
        float z = s_invZ[i >> 7];       // i*4/512
        v.x *= z; v.y *= z; v.z *= z; v.w *= z;
        sm4[i] = v;
    }
    __syncthreads();

    const int row = blockIdx.x*8 + warp;
    const float4* wr = reinterpret_cast<const float4*>(Wcv + row*C_);
    float acc[B_];
    #pragma unroll
    for (int b = 0; b < B_; b++) acc[b] = 0.f;
    #pragma unroll
    for (int j = 0; j < C_/(4*32); j++) {
        float4 w4 = wr[lane + 32*j];
        #pragma unroll
        for (int b = 0; b < B_; b++)
            acc[b] += dot4(w4, sm4[b*(C_/4) + lane + 32*j]);
    }
    #pragma unroll
    for (int b = 0; b < B_; b++) {
        float r = warpReduceSum(acc[b]);
        if (lane == 0) g_ctx[b*INNER_ + row] = r;
    }
}

// ---------------------------------------------------------------------------
// GEMM z = Wcz(512x256) @ ctx(256 x 16). grid 64, block 256.
// ---------------------------------------------------------------------------
__global__ __launch_bounds__(256)
void k_gemm_z(const float* __restrict__ Wcz) {
    const int tid = threadIdx.x;
    const int lane = tid & 31, warp = tid >> 5;
    __shared__ __align__(16) float s_ctx[B_*INNER_];   // 16 KB

    float4* sm4 = reinterpret_cast<float4*>(s_ctx);
    const float4* gm4 = reinterpret_cast<const float4*>(g_ctx);
    #pragma unroll
    for (int i = tid; i < B_*INNER_/4; i += 256) sm4[i] = gm4[i];
    __syncthreads();

    const int row = blockIdx.x*8 + warp;               // [0,512)
    const float4* wr = reinterpret_cast<const float4*>(Wcz + row*INNER_);
    float acc[B_];
    #pragma unroll
    for (int b = 0; b < B_; b++) acc[b] = 0.f;
    #pragma unroll
    for (int j = 0; j < INNER_/(4*32); j++) {
        float4 w4 = wr[lane + 32*j];
        #pragma unroll
        for (int b = 0; b < B_; b++)
            acc[b] += dot4(w4, sm4[b*(INNER_/4) + lane + 32*j]);
    }
    #pragma unroll
    for (int b = 0; b < B_; b++) {
        float r = warpReduceSum(acc[b]);
        if (lane == 0) g_z[b*C_ + row] = r;
    }
}

// ---------------------------------------------------------------------------
// LayerNorm + sigmoid -> mask. grid B_, block 512.
// ---------------------------------------------------------------------------
__global__ __launch_bounds__(512)
void k_ln(const float* __restrict__ gamma, const float* __restrict__ beta) {
    const int b = blockIdx.x;
    const int tid = threadIdx.x;
    float z = g_z[b*C_ + tid];
    float mu  = blockReduceSum(z) * (1.0f/(float)C_);
    float d   = z - mu;
    float var = blockReduceSum(d*d) * (1.0f/(float)C_);
    float zn  = d * rsqrtf(var + 1e-5f) * gamma[tid] + beta[tid];
    g_mask[b*C_ + tid] = 1.0f/(1.0f + __expf(-zn));
}

// ---------------------------------------------------------------------------
// Final: out = x * (mask[b,c] + sig_ctx[b,n])
// ---------------------------------------------------------------------------
__global__ __launch_bounds__(256)
void k_final(const float* __restrict__ x, float* __restrict__ out) {
    const float4* x4  = reinterpret_cast<const float4*>(x);
    float4*       o4  = reinterpret_cast<float4*>(out);
    const float4* sc4 = reinterpret_cast<const float4*>(g_sigctx);
    const int total4 = B_*C_*HW4;
    for (int i = blockIdx.x*blockDim.x + threadIdx.x; i < total4;
         i += gridDim.x*blockDim.x) {
        const int n4 = i & (HW4 - 1);
        const int bc = i >> 10;          // b*512 + c
        const int b  = bc >> 9;
        const float  m = g_mask[bc];     // warp-uniform -> single sector
        const float4 s = sc4[(b << 10) + n4];
        float4 v = x4[i];
        float4 r;
        r.x = v.x*(m + s.x);
        r.y = v.y*(m + s.y);
        r.z = v.z*(m + s.z);
        r.w = v.w*(m + s.w);
        o4[i] = r;
    }
}

// ---------------------------------------------------------------------------
// Launch
// ---------------------------------------------------------------------------
extern "C" void kernel_launch(void* const* d_in, const int* in_sizes, int n_in,
                              void* d_out, int out_size) {
    const float* x     = (const float*)d_in[0];
    const float* Wsq   = (const float*)d_in[1];
    const float* Wsv   = (const float*)d_in[2];
    const float* Wcq   = (const float*)d_in[3];
    const float* Wcv   = (const float*)d_in[4];
    const float* Wcz   = (const float*)d_in[5];
    const float* gamma = (const float*)d_in[6];
    const float* beta  = (const float*)d_in[7];
    float* out = (float*)d_out;

    dim3 gpass(NTILE*NCGRP, B_);   // 128 x 16 = 2048 CTAs
    dim3 gred(5, B_);              // 80 CTAs
    dim3 gweff(KCH, B_);           // 256 CTAs
    k_pass1   <<<gpass, NT>>>(x, Wcq);
    k_red1    <<<gred, 256>>>();
    k_gemm_a  <<<32, 256>>>(Wsq);
    k_weff    <<<gweff, 128>>>(Wsv);
    k_pass2   <<<gpass, NT>>>(x);
    k_red2    <<<gred, 256>>>();
    k_gemm_ctx<<<32, 256>>>(Wcv);
    k_gemm_z  <<<64, 256>>>(Wcz);
    k_ln      <<<B_, 512>>>(gamma, beta);
    k_final   <<<8192, 256>>>(x, out);
}